// round 11
// baseline (speedup 1.0000x reference)
#include <cuda_runtime.h>
#include <math.h>
#include <stdint.h>

#define D_  1024
#define H_  16
#define DH_ 64
#define F_  4096
#define E_  8
#define K_  2
#define B_  2
#define S_  2048
#define N_  (B_ * S_)          // 4096 tokens
#define BH_ (B_ * H_)          // 32
#define ND_ ((long)N_ * D_)    // 4194304

// ---------------- scratch (device globals; no allocation allowed) -------------
__device__ float g_q[N_ * D_];
__device__ float g_k[N_ * D_];
__device__ float g_v[N_ * D_];
__device__ float g_attn[N_ * D_];
__device__ float g_t[N_ * D_];
__device__ float g_x1[N_ * D_];
__device__ float g_x2[N_ * D_];
__device__ float g_s[(long)N_ * K_ * F_];   // MoE hidden (128MB)
__device__ float g_y[(long)N_ * K_ * D_];   // MoE expert outputs per dispatch row

__device__ int   g_topi[N_ * K_];
__device__ float g_gate[N_ * K_];
__device__ int   g_drow[N_ * K_];           // token -> its dispatch rows
__device__ int   g_cnt[E_];
__device__ int   g_off[E_];
__device__ int   g_cur[E_];
__device__ int   g_dtok[N_ * K_];
__device__ float g_probs[N_ * E_];
__device__ int   g_loadcnt[E_];

// ---------------- mma / cp.async / ldmatrix helpers ----------------------------
__device__ __forceinline__ void mma_tf32(float* c, const uint32_t* a, const uint32_t* b)
{
    asm volatile(
        "mma.sync.aligned.m16n8k8.row.col.f32.tf32.tf32.f32 "
        "{%0,%1,%2,%3}, {%4,%5,%6,%7}, {%8,%9}, {%0,%1,%2,%3};\n"
        : "+f"(c[0]), "+f"(c[1]), "+f"(c[2]), "+f"(c[3])
        : "r"(a[0]), "r"(a[1]), "r"(a[2]), "r"(a[3]), "r"(b[0]), "r"(b[1]));
}

__device__ __forceinline__ void ldsm4(uint32_t* r, uint32_t addr)
{
    asm volatile("ldmatrix.sync.aligned.m8n8.x4.shared.b16 {%0,%1,%2,%3}, [%4];\n"
                 : "=r"(r[0]), "=r"(r[1]), "=r"(r[2]), "=r"(r[3]) : "r"(addr));
}

__device__ __forceinline__ void ldsm2(uint32_t* r, uint32_t addr)
{
    asm volatile("ldmatrix.sync.aligned.m8n8.x2.shared.b16 {%0,%1}, [%2];\n"
                 : "=r"(r[0]), "=r"(r[1]) : "r"(addr));
}

__device__ __forceinline__ void cp16(uint32_t dst, const void* src, int srcbytes)
{
    asm volatile("cp.async.cg.shared.global [%0], [%1], 16, %2;\n"
                 :: "r"(dst), "l"(src), "r"(srcbytes));
}
#define CP_COMMIT asm volatile("cp.async.commit_group;\n")
#define CP_WAIT0  asm volatile("cp.async.wait_group 0;\n")

// ---------------- double-buffered tf32 GEMM core (128x128 tile, TBK=32) --------
// 256 threads, 8 warps in 2(M)x4(N), warp tile 64x32, ONE sync per 64 MMAs.
//   wait(stage k) -> sync -> issue prefetch(k+1 into other buf) -> compute(k)
// Shared memory is DYNAMIC (71,680 B > 48 KB static limit):
//   [0, 2*128*AST) = A stages, [2*128*AST, +2*TBK*BST) = B stages.
// A smem row-major stride 36 words (ldsm phase: bank (4r+c) -> conflict-free).
// B smem row-major stride 136 (scalar LDS, conflict-free).
#define TBK 32
#define AST 36
#define BST 136
#define A_STG (128 * AST)
#define B_STG (TBK * BST)
#define GEMM_SMEM_BYTES ((2 * A_STG + 2 * B_STG) * 4)   // 71680

template<bool GATHER, bool RELU>
__device__ __forceinline__ void gemm128_db(
    const float* __restrict__ A, int lda,
    const float* __restrict__ B, int ldb,
    float* __restrict__ C, int ldc,
    int M, int K, int n0,
    const float* __restrict__ bias,
    const int* __restrict__ gidx)
{
    extern __shared__ float smg[];
    float* As = smg;
    float* Bs = smg + 2 * A_STG;

    const int tid = threadIdx.x;
    const int m0 = blockIdx.y * 128;
    if (m0 >= M) return;

    const int w = tid >> 5;
    const int lane = tid & 31;
    const int gid = lane >> 2;
    const int tig = lane & 3;
    const int wm = (w & 1) * 64;
    const int wn = (w >> 1) * 32;

    float acc[4][4][4];
#pragma unroll
    for (int mi = 0; mi < 4; mi++)
#pragma unroll
        for (int ni = 0; ni < 4; ni++)
#pragma unroll
            for (int r = 0; r < 4; r++) acc[mi][ni][r] = 0.f;

    // A loader: row = tid>>1 (128 rows), 16 floats starting at (tid&1)*16
    const int ar = tid >> 1;
    const int ac = (tid & 1) * 16;
    const bool avalid = (m0 + ar) < M;
    long grow = 0;
    if (avalid) grow = GATHER ? (long)gidx[m0 + ar] : (long)(m0 + ar);
    const float* Ap = A + grow * (long)lda + ac;
    const int ab = avalid ? 16 : 0;

    // B loader: row = tid>>3 (32 rows), 16 floats at (tid&7)*16
    const int br = tid >> 3;
    const int bc = (tid & 7) * 16;
    const float* Bp = B + (long)br * ldb + n0 + bc;

    uint32_t adst[2], bdst[2];
    adst[0] = (uint32_t)__cvta_generic_to_shared(&As[ar * AST + ac]);
    adst[1] = (uint32_t)__cvta_generic_to_shared(&As[A_STG + ar * AST + ac]);
    bdst[0] = (uint32_t)__cvta_generic_to_shared(&Bs[br * BST + bc]);
    bdst[1] = (uint32_t)__cvta_generic_to_shared(&Bs[B_STG + br * BST + bc]);

    // ldmatrix lane-address: lanes 0-15 -> rows 0-15 col 0; 16-31 -> rows 0-15 col 4
    const int rowoff = lane & 15;
    const int coloff = (lane >> 4) * 4;
    uint32_t albase[2];
    albase[0] = (uint32_t)__cvta_generic_to_shared(&As[(wm + rowoff) * AST + coloff]);
    albase[1] = (uint32_t)__cvta_generic_to_shared(&As[A_STG + (wm + rowoff) * AST + coloff]);

    const int KT = K / TBK;

    // prologue: stage 0
#pragma unroll
    for (int i = 0; i < 4; i++) {
        cp16(adst[0] + i * 16, Ap + i * 4, ab);
        cp16(bdst[0] + i * 16, Bp + i * 4, 16);
    }
    CP_COMMIT;

    for (int kt = 0; kt < KT; kt++) {
        const int cur = kt & 1;
        CP_WAIT0;
        __syncthreads();
        if (kt + 1 < KT) {
            const float* ap = Ap + (kt + 1) * TBK;
            const float* bp = Bp + (long)(kt + 1) * TBK * ldb;
#pragma unroll
            for (int i = 0; i < 4; i++) {
                cp16(adst[cur ^ 1] + i * 16, ap + i * 4, ab);
                cp16(bdst[cur ^ 1] + i * 16, bp + i * 4, 16);
            }
            CP_COMMIT;
        }

        const float* bs = Bs + cur * B_STG;
        const uint32_t alb = albase[cur];
#pragma unroll
        for (int ks = 0; ks < TBK; ks += 8) {
            uint32_t af[4][4], bf[4][2];
#pragma unroll
            for (int mi = 0; mi < 4; mi++)
                ldsm4(af[mi], alb + (mi * 16 * AST + ks) * 4);
#pragma unroll
            for (int ni = 0; ni < 4; ni++) {
                const int ncol = wn + ni * 8 + gid;
                bf[ni][0] = __float_as_uint(bs[(ks + tig) * BST + ncol]);
                bf[ni][1] = __float_as_uint(bs[(ks + tig + 4) * BST + ncol]);
            }
#pragma unroll
            for (int mi = 0; mi < 4; mi++)
#pragma unroll
                for (int ni = 0; ni < 4; ni++)
                    mma_tf32(acc[mi][ni], af[mi], bf[ni]);
        }
    }

    // epilogue (c0:(r,c) c1:(r,c+1) c2:(r+8,c) c3:(r+8,c+1))
#pragma unroll
    for (int mi = 0; mi < 4; mi++) {
#pragma unroll
        for (int half = 0; half < 2; half++) {
            const int row = m0 + wm + mi * 16 + gid + half * 8;
            if (row >= M) continue;
            float* cp = C + (long)row * ldc;
#pragma unroll
            for (int ni = 0; ni < 4; ni++) {
                const int col = n0 + wn + ni * 8 + tig * 2;
                float v0 = acc[mi][ni][half * 2 + 0];
                float v1 = acc[mi][ni][half * 2 + 1];
                if (bias) { v0 += bias[col]; v1 += bias[col + 1]; }
                if constexpr (RELU) { v0 = fmaxf(v0, 0.f); v1 = fmaxf(v1, 0.f); }
                *(float2*)(cp + col) = make_float2(v0, v1);
            }
        }
    }
}

// ---------------- GEMM wrappers -------------------------------------------------
__global__ void __launch_bounds__(256) k_proj3(
    const float* a0, const float* a1, const float* a2,
    const float* w0, const float* w1, const float* w2,
    const float* bi0, const float* bi1, const float* bi2,
    float* c0, float* c1, float* c2)
{
    const float *A, *W, *bi;
    float* C;
    if (blockIdx.z == 0)      { A = a0; W = w0; bi = bi0; C = c0; }
    else if (blockIdx.z == 1) { A = a1; W = w1; bi = bi1; C = c1; }
    else                      { A = a2; W = w2; bi = bi2; C = c2; }
    gemm128_db<false, false>(A, D_, W, D_, C, D_, N_, D_, blockIdx.x * 128,
                             bi, nullptr);
}

__global__ void __launch_bounds__(256) k_proj1(
    const float* __restrict__ A, const float* __restrict__ W,
    const float* __restrict__ bi, float* __restrict__ C)
{
    gemm128_db<false, false>(A, D_, W, D_, C, D_, N_, D_, blockIdx.x * 128,
                             bi, nullptr);
}

// MoE FF1: h = relu(gather(x2) @ W1[e] + b1[e]) into g_s
__global__ void __launch_bounds__(256) k_ff1(
    const float* __restrict__ W1, const float* __restrict__ B1)
{
    const int e = blockIdx.z;
    const int cnt = g_cnt[e];
    if ((int)(blockIdx.y * 128) >= cnt) return;
    const int off = g_off[e];
    gemm128_db<true, true>(
        g_x2, D_, W1 + (long)e * D_ * F_, F_,
        g_s + (long)off * F_, F_,
        cnt, D_, blockIdx.x * 128, B1 + (long)e * F_,
        g_dtok + off);
}

// MoE FF2: y[dispatch_row] = h @ W2[e] + b2[e]   (plain stores)
__global__ void __launch_bounds__(256) k_ff2(
    const float* __restrict__ W2, const float* __restrict__ B2)
{
    const int e = blockIdx.z;
    const int cnt = g_cnt[e];
    if ((int)(blockIdx.y * 128) >= cnt) return;
    const int off = g_off[e];
    gemm128_db<false, false>(
        g_s + (long)off * F_, F_, W2 + (long)e * F_ * D_, D_,
        g_y + (long)off * D_, D_,
        cnt, F_, blockIdx.x * 128, B2 + (long)e * D_,
        nullptr);
}

// ---------------- flash attention (single-buffer K/V, 105KB -> 2 CTAs/SM) ------
#define QS_OFF 0
#define PS_OFF 8704
#define KS_OFF 17408
#define VS_OFF 21760
#define FL_SMEM_WORDS 26368   // *4 = 105472 bytes

__global__ void __launch_bounds__(256) k_flash()
{
    extern __shared__ float sm[];
#define QS(r, c) sm[QS_OFF + (r) * 68 + (c)]
#define PS(r, c) sm[PS_OFF + (r) * 68 + (c)]
#define KS(r, c) sm[KS_OFF + (r) * 68 + (c)]
#define VS(r, c) sm[VS_OFF + (r) * 72 + (c)]

    const int tid = threadIdx.x;
    const int w = tid >> 5;
    const int lane = tid & 31;
    const int gid = lane >> 2;
    const int tig = lane & 3;
    const int wm = w * 16;

    const int qb = blockIdx.x;
    const int z = blockIdx.y;
    const int b = z >> 4, h = z & 15;
    const int q0 = qb * 128;

    // ldmatrix lane-addresses
    const int rowoff = lane & 15;
    const int coloff = (lane >> 4) * 4;
    const uint32_t qlb = (uint32_t)__cvta_generic_to_shared(
        &QS(wm + rowoff, coloff));
    const uint32_t plb = (uint32_t)__cvta_generic_to_shared(
        &PS(wm + rowoff, coloff));
    const int krow = lane & 7;
    const int kcol = ((lane >> 3) & 1) * 4;
    const uint32_t klb = (uint32_t)__cvta_generic_to_shared(&KS(krow, kcol));

    // Q tile (128 x 64)
    {
        const int r = tid >> 1;
        const int c0 = (tid & 1) * 32;
        const float* qp = g_q + ((long)(b * S_ + q0 + r)) * D_ + h * DH_ + c0;
        uint32_t qd = (uint32_t)__cvta_generic_to_shared(&QS(r, c0));
#pragma unroll
        for (int i = 0; i < 8; i++) cp16(qd + i * 16, qp + i * 4, 16);
    }

    const int ls = tid >> 2;
    const int ld0 = (tid & 3) * 16;
    const long kvb = ((long)(b * S_ + ls)) * D_ + h * DH_ + ld0;
    uint32_t kd = (uint32_t)__cvta_generic_to_shared(&KS(ls, ld0));
    uint32_t vd = (uint32_t)__cvta_generic_to_shared(&VS(ls, ld0));

    {
        const float* kp = g_k + kvb;
        const float* vp = g_v + kvb;
#pragma unroll
        for (int i = 0; i < 4; i++) {
            cp16(kd + i * 16, kp + i * 4, 16);
            cp16(vd + i * 16, vp + i * 4, 16);
        }
    }
    CP_COMMIT;

    float m0v = -3.4e38f, m1v = -3.4e38f;
    float l0 = 0.f, l1 = 0.f;
    float o[8][4];
#pragma unroll
    for (int ni = 0; ni < 8; ni++)
#pragma unroll
        for (int r = 0; r < 4; r++) o[ni][r] = 0.f;

    const int J = S_ / 64;
    for (int j = 0; j < J; j++) {
        CP_WAIT0;
        __syncthreads();

        // S = Q @ K^T (warp: 16 rows x 64 keys), then * 0.125
        float sacc[8][4];
#pragma unroll
        for (int ni = 0; ni < 8; ni++)
#pragma unroll
            for (int r = 0; r < 4; r++) sacc[ni][r] = 0.f;
#pragma unroll
        for (int ks = 0; ks < 64; ks += 8) {
            uint32_t af[4];
            ldsm4(af, qlb + ks * 4);
#pragma unroll
            for (int ni = 0; ni < 8; ni++) {
                uint32_t bf[2];
                ldsm2(bf, klb + (ni * 8 * 68 + ks) * 4);
                mma_tf32(sacc[ni], af, bf);
            }
        }
#pragma unroll
        for (int ni = 0; ni < 8; ni++)
#pragma unroll
            for (int r = 0; r < 4; r++) sacc[ni][r] *= 0.125f;

        // online softmax
        float mx0 = -3.4e38f, mx1 = -3.4e38f;
#pragma unroll
        for (int ni = 0; ni < 8; ni++) {
            mx0 = fmaxf(mx0, fmaxf(sacc[ni][0], sacc[ni][1]));
            mx1 = fmaxf(mx1, fmaxf(sacc[ni][2], sacc[ni][3]));
        }
        mx0 = fmaxf(mx0, __shfl_xor_sync(0xffffffffu, mx0, 1));
        mx0 = fmaxf(mx0, __shfl_xor_sync(0xffffffffu, mx0, 2));
        mx1 = fmaxf(mx1, __shfl_xor_sync(0xffffffffu, mx1, 1));
        mx1 = fmaxf(mx1, __shfl_xor_sync(0xffffffffu, mx1, 2));
        const float mn0 = fmaxf(m0v, mx0);
        const float mn1 = fmaxf(m1v, mx1);
        const float a0 = __expf(m0v - mn0);
        const float a1 = __expf(m1v - mn1);
        m0v = mn0; m1v = mn1;

        float s0 = 0.f, s1 = 0.f;
#pragma unroll
        for (int ni = 0; ni < 8; ni++) {
            float p0 = __expf(sacc[ni][0] - mn0);
            float p1 = __expf(sacc[ni][1] - mn0);
            float p2 = __expf(sacc[ni][2] - mn1);
            float p3 = __expf(sacc[ni][3] - mn1);
            s0 += p0 + p1; s1 += p2 + p3;
            const int col = ni * 8 + tig * 2;
            PS(wm + gid, col) = p0;
            PS(wm + gid, col + 1) = p1;
            PS(wm + gid + 8, col) = p2;
            PS(wm + gid + 8, col + 1) = p3;
        }
        s0 += __shfl_xor_sync(0xffffffffu, s0, 1);
        s0 += __shfl_xor_sync(0xffffffffu, s0, 2);
        s1 += __shfl_xor_sync(0xffffffffu, s1, 1);
        s1 += __shfl_xor_sync(0xffffffffu, s1, 2);
        l0 = l0 * a0 + s0;
        l1 = l1 * a1 + s1;

#pragma unroll
        for (int ni = 0; ni < 8; ni++) {
            o[ni][0] *= a0; o[ni][1] *= a0;
            o[ni][2] *= a1; o[ni][3] *= a1;
        }
        __syncwarp();

        // O += P @ V
#pragma unroll
        for (int ks = 0; ks < 64; ks += 8) {
            uint32_t af[4];
            ldsm4(af, plb + ks * 4);
#pragma unroll
            for (int ni = 0; ni < 8; ni++) {
                uint32_t bf[2];
                bf[0] = __float_as_uint(VS(ks + tig, ni * 8 + gid));
                bf[1] = __float_as_uint(VS(ks + tig + 4, ni * 8 + gid));
                mma_tf32(o[ni], af, bf);
            }
        }
        __syncthreads();

        if (j + 1 < J) {
            const float* kp = g_k + kvb + (long)(j + 1) * 64 * D_;
            const float* vp = g_v + kvb + (long)(j + 1) * 64 * D_;
#pragma unroll
            for (int i = 0; i < 4; i++) {
                cp16(kd + i * 16, kp + i * 4, 16);
                cp16(vd + i * 16, vp + i * 4, 16);
            }
            CP_COMMIT;
        }
    }

    // write O (normalized)
    const float inv0 = 1.f / l0;
    const float inv1 = 1.f / l1;
    const long r0 = (long)(b * S_ + q0 + wm + gid) * D_ + h * DH_;
    const long r1 = r0 + 8 * D_;
#pragma unroll
    for (int ni = 0; ni < 8; ni++) {
        const int col = ni * 8 + tig * 2;
        *(float2*)(g_attn + r0 + col) = make_float2(o[ni][0] * inv0, o[ni][1] * inv0);
        *(float2*)(g_attn + r1 + col) = make_float2(o[ni][2] * inv1, o[ni][3] * inv1);
    }
#undef QS
#undef PS
#undef KS
#undef VS
}

// ---------------- elementwise / LN ---------------------------------------------
__global__ void k_zero()
{
    int i = threadIdx.x;
    if (i < E_) { g_cnt[i] = 0; g_cur[i] = 0; g_loadcnt[i] = 0; }
}

__global__ void k_addln(const float* __restrict__ a, const float* __restrict__ b,
                        const float* __restrict__ g, const float* __restrict__ be,
                        float* __restrict__ out)
{
    __shared__ float buf[D_];
    __shared__ float red[256];
    const int t = blockIdx.x;
    const int tid = threadIdx.x;
    const float* pa = a + (long)t * D_;
    const float* pb = b + (long)t * D_;
    float s = 0.f;
    for (int i = tid; i < D_; i += 256) { float v = pa[i] + pb[i]; buf[i] = v; s += v; }
    red[tid] = s; __syncthreads();
    for (int o = 128; o > 0; o >>= 1) { if (tid < o) red[tid] += red[tid + o]; __syncthreads(); }
    float mean = red[0] * (1.f / D_);
    __syncthreads();
    float vs = 0.f;
    for (int i = tid; i < D_; i += 256) { float d = buf[i] - mean; vs += d * d; }
    red[tid] = vs; __syncthreads();
    for (int o = 128; o > 0; o >>= 1) { if (tid < o) red[tid] += red[tid + o]; __syncthreads(); }
    float rstd = rsqrtf(red[0] * (1.f / D_) + 1e-5f);
    float* po = out + (long)t * D_;
    for (int i = tid; i < D_; i += 256)
        po[i] = (buf[i] - mean) * rstd * g[i] + be[i];
}

// final LN fused with MoE combine: out = LN(x2 + g0*y[d0] + g1*y[d1])
__global__ void k_addln_moe(const float* __restrict__ a,
                            const float* __restrict__ g, const float* __restrict__ be,
                            float* __restrict__ out)
{
    __shared__ float buf[D_];
    __shared__ float red[256];
    const int t = blockIdx.x;
    const int tid = threadIdx.x;
    const float* pa = a + (long)t * D_;
    const float* y0 = g_y + (long)g_drow[t * 2] * D_;
    const float* y1 = g_y + (long)g_drow[t * 2 + 1] * D_;
    const float gt0 = g_gate[t * 2];
    const float gt1 = g_gate[t * 2 + 1];
    float s = 0.f;
    for (int i = tid; i < D_; i += 256) {
        float v = pa[i] + gt0 * y0[i] + gt1 * y1[i];
        buf[i] = v; s += v;
    }
    red[tid] = s; __syncthreads();
    for (int o = 128; o > 0; o >>= 1) { if (tid < o) red[tid] += red[tid + o]; __syncthreads(); }
    float mean = red[0] * (1.f / D_);
    __syncthreads();
    float vs = 0.f;
    for (int i = tid; i < D_; i += 256) { float d = buf[i] - mean; vs += d * d; }
    red[tid] = vs; __syncthreads();
    for (int o = 128; o > 0; o >>= 1) { if (tid < o) red[tid] += red[tid + o]; __syncthreads(); }
    float rstd = rsqrtf(red[0] * (1.f / D_) + 1e-5f);
    float* po = out + (long)t * D_;
    for (int i = tid; i < D_; i += 256)
        po[i] = (buf[i] - mean) * rstd * g[i] + be[i];
}

// ---------------- router / dispatch / aux --------------------------------------
__device__ __forceinline__ void router_core(const float* __restrict__ x,
                                            const float* __restrict__ rw,
                                            const float* __restrict__ rb,
                                            int lane, float* probs_out,
                                            int* i1_out, int* i2_out)
{
    float le[E_];
#pragma unroll
    for (int e = 0; e < E_; e++) le[e] = 0.f;
    for (int d0 = lane * 4; d0 < D_; d0 += 128) {
        float4 xv = *(const float4*)(x + d0);
        float xa[4] = {xv.x, xv.y, xv.z, xv.w};
#pragma unroll
        for (int r = 0; r < 4; r++) {
            const float* w = rw + (long)(d0 + r) * E_;
            float4 w0 = *(const float4*)(w);
            float4 w1 = *(const float4*)(w + 4);
            le[0] = fmaf(xa[r], w0.x, le[0]); le[1] = fmaf(xa[r], w0.y, le[1]);
            le[2] = fmaf(xa[r], w0.z, le[2]); le[3] = fmaf(xa[r], w0.w, le[3]);
            le[4] = fmaf(xa[r], w1.x, le[4]); le[5] = fmaf(xa[r], w1.y, le[5]);
            le[6] = fmaf(xa[r], w1.z, le[6]); le[7] = fmaf(xa[r], w1.w, le[7]);
        }
    }
#pragma unroll
    for (int e = 0; e < E_; e++)
        for (int o = 16; o > 0; o >>= 1) le[e] += __shfl_xor_sync(0xffffffffu, le[e], o);
    float mx = -3.4e38f;
#pragma unroll
    for (int e = 0; e < E_; e++) { le[e] += rb[e]; mx = fmaxf(mx, le[e]); }
    float sum = 0.f;
#pragma unroll
    for (int e = 0; e < E_; e++) { le[e] = expf(le[e] - mx); sum += le[e]; }
    float inv = 1.f / sum;
#pragma unroll
    for (int e = 0; e < E_; e++) { le[e] *= inv; probs_out[e] = le[e]; }
    int i1 = 0;
    for (int e = 1; e < E_; e++) if (le[e] > le[i1]) i1 = e;
    int i2 = (i1 == 0) ? 1 : 0;
    for (int e = 0; e < E_; e++) if (e != i1 && le[e] > le[i2]) i2 = e;
    *i1_out = i1; *i2_out = i2;
}

__global__ void k_router(const float* __restrict__ rw, const float* __restrict__ rb)
{
    const int warp = threadIdx.x >> 5, lane = threadIdx.x & 31;
    const int t = blockIdx.x * 8 + warp;
    if (t >= N_) return;
    float probs[E_]; int i1, i2;
    router_core(g_x2 + (long)t * D_, rw, rb, lane, probs, &i1, &i2);
    if (lane == 0) {
        float gs = probs[i1] + probs[i2];
        g_topi[t * 2] = i1; g_topi[t * 2 + 1] = i2;
        g_gate[t * 2] = probs[i1] / gs; g_gate[t * 2 + 1] = probs[i2] / gs;
        atomicAdd(&g_cnt[i1], 1); atomicAdd(&g_cnt[i2], 1);
    }
}

__global__ void k_scan()
{
    if (threadIdx.x == 0) {
        int s = 0;
        for (int e = 0; e < E_; e++) { g_off[e] = s; s += g_cnt[e]; }
    }
}

__global__ void k_fill()
{
    int t = blockIdx.x * 256 + threadIdx.x;
    if (t >= N_) return;
#pragma unroll
    for (int k = 0; k < K_; k++) {
        int e = g_topi[t * K_ + k];
        int p = atomicAdd(&g_cur[e], 1);
        int d = g_off[e] + p;
        g_dtok[d] = t;
        g_drow[t * K_ + k] = d;
    }
}

__global__ void k_aux_router(const float* __restrict__ X,
                             const float* __restrict__ rw, const float* __restrict__ rb)
{
    const int warp = threadIdx.x >> 5, lane = threadIdx.x & 31;
    const int t = blockIdx.x * 8 + warp;
    if (t >= N_) return;
    float probs[E_]; int i1, i2;
    router_core(X + (long)t * D_, rw, rb, lane, probs, &i1, &i2);
    if (lane == 0) {
#pragma unroll
        for (int e = 0; e < E_; e++) g_probs[t * E_ + e] = probs[e];
        atomicAdd(&g_loadcnt[i1], 1); atomicAdd(&g_loadcnt[i2], 1);
    }
}

__global__ void k_aux_reduce(float* __restrict__ out, int write)
{
    __shared__ float red[256];
    const int tid = threadIdx.x;
    float imp[E_];
#pragma unroll
    for (int e = 0; e < E_; e++) imp[e] = 0.f;
    for (int t = tid; t < N_; t += 256)
#pragma unroll
        for (int e = 0; e < E_; e++) imp[e] += g_probs[t * E_ + e];
    float aux = 0.f;
    for (int e = 0; e < E_; e++) {
        red[tid] = imp[e]; __syncthreads();
        for (int o = 128; o > 0; o >>= 1) { if (tid < o) red[tid] += red[tid + o]; __syncthreads(); }
        if (tid == 0)
            aux += (red[0] / (float)N_) * ((float)g_loadcnt[e] / (float)(N_ * K_));
        __syncthreads();
    }
    if (tid == 0 && write) out[ND_] = aux * (float)E_;
}

// ---------------- launch ------------------------------------------------------
extern "C" void kernel_launch(void* const* d_in, const int* in_sizes, int n_in,
                              void* d_out, int out_size)
{
    (void)in_sizes; (void)n_in;
    const float* x     = (const float*)d_in[0];
    const float* enc   = (const float*)d_in[1];
    const float* sa_wq = (const float*)d_in[2];
    const float* sa_bq = (const float*)d_in[3];
    const float* sa_wk = (const float*)d_in[4];
    const float* sa_bk = (const float*)d_in[5];
    const float* sa_wv = (const float*)d_in[6];
    const float* sa_bv = (const float*)d_in[7];
    const float* sa_wo = (const float*)d_in[8];
    const float* sa_bo = (const float*)d_in[9];
    const float* ca_wq = (const float*)d_in[10];
    const float* ca_bq = (const float*)d_in[11];
    const float* ca_wk = (const float*)d_in[12];
    const float* ca_bk = (const float*)d_in[13];
    const float* ca_wv = (const float*)d_in[14];
    const float* ca_bv = (const float*)d_in[15];
    const float* ca_wo = (const float*)d_in[16];
    const float* ca_bo = (const float*)d_in[17];
    const float* n1_g  = (const float*)d_in[18];
    const float* n1_b  = (const float*)d_in[19];
    const float* n2_g  = (const float*)d_in[20];
    const float* n2_b  = (const float*)d_in[21];
    const float* n3_g  = (const float*)d_in[22];
    const float* n3_b  = (const float*)d_in[23];
    const float* r_w   = (const float*)d_in[24];
    const float* r_b   = (const float*)d_in[25];
    const float* e_w1  = (const float*)d_in[26];
    const float* e_b1  = (const float*)d_in[27];
    const float* e_w2  = (const float*)d_in[28];
    const float* e_b2  = (const float*)d_in[29];
    float* out = (float*)d_out;

    float *pq, *pk, *pv, *pattn, *pt, *px1, *px2;
    cudaGetSymbolAddress((void**)&pq, g_q);
    cudaGetSymbolAddress((void**)&pk, g_k);
    cudaGetSymbolAddress((void**)&pv, g_v);
    cudaGetSymbolAddress((void**)&pattn, g_attn);
    cudaGetSymbolAddress((void**)&pt, g_t);
    cudaGetSymbolAddress((void**)&px1, g_x1);
    cudaGetSymbolAddress((void**)&px2, g_x2);

    static int s_attr_done = 0;
    if (!s_attr_done) {
        cudaFuncSetAttribute(k_flash, cudaFuncAttributeMaxDynamicSharedMemorySize,
                             FL_SMEM_WORDS * 4);
        cudaFuncSetAttribute(k_proj3, cudaFuncAttributeMaxDynamicSharedMemorySize,
                             GEMM_SMEM_BYTES);
        cudaFuncSetAttribute(k_proj1, cudaFuncAttributeMaxDynamicSharedMemorySize,
                             GEMM_SMEM_BYTES);
        cudaFuncSetAttribute(k_ff1, cudaFuncAttributeMaxDynamicSharedMemorySize,
                             GEMM_SMEM_BYTES);
        cudaFuncSetAttribute(k_ff2, cudaFuncAttributeMaxDynamicSharedMemorySize,
                             GEMM_SMEM_BYTES);
        s_attr_done = 1;
    }

    dim3 blk(256);
    dim3 gP3(D_ / 128, N_ / 128, 3);           // (8, 32, 3)
    dim3 gP1(D_ / 128, N_ / 128);              // (8, 32)
    dim3 gFlash(S_ / 128, BH_);                // (16, 32)

    k_zero<<<1, 32>>>();

    // ---- self attention ----
    k_proj3<<<gP3, blk, GEMM_SMEM_BYTES>>>(x, x, x, sa_wq, sa_wk, sa_wv,
                                           sa_bq, sa_bk, sa_bv, pq, pk, pv);
    k_flash<<<gFlash, blk, FL_SMEM_WORDS * 4>>>();
    k_proj1<<<gP1, blk, GEMM_SMEM_BYTES>>>(pattn, sa_wo, sa_bo, pt);
    k_addln<<<N_, blk>>>(x, pt, n1_g, n1_b, px1);

    // ---- cross attention ----
    k_proj3<<<gP3, blk, GEMM_SMEM_BYTES>>>(px1, enc, enc, ca_wq, ca_wk, ca_wv,
                                           ca_bq, ca_bk, ca_bv, pq, pk, pv);
    k_flash<<<gFlash, blk, FL_SMEM_WORDS * 4>>>();
    k_proj1<<<gP1, blk, GEMM_SMEM_BYTES>>>(pattn, ca_wo, ca_bo, pt);
    k_addln<<<N_, blk>>>(px1, pt, n2_g, n2_b, px2);

    // ---- MoE (sparse top-2 dispatch, no atomic combine) ----
    k_router<<<N_ / 8, blk>>>(r_w, r_b);
    k_scan<<<1, 32>>>();
    k_fill<<<N_ / 256, blk>>>();
    k_ff1<<<dim3(F_ / 128, 64, E_), blk, GEMM_SMEM_BYTES>>>(e_w1, e_b1);
    k_ff2<<<dim3(D_ / 128, 64, E_), blk, GEMM_SMEM_BYTES>>>(e_w2, e_b2);
    k_addln_moe<<<N_, blk>>>(px2, n3_g, n3_b, out);

    // ---- aux loss on final output ----
    k_aux_router<<<N_ / 8, blk>>>(out, r_w, r_b);
    k_aux_reduce<<<1, blk>>>(out, ((long)out_size > ND_) ? 1 : 0);
}

// round 12
// speedup vs baseline: 1.0830x; 1.0830x over previous
#include <cuda_runtime.h>
#include <math.h>
#include <stdint.h>

#define D_  1024
#define H_  16
#define DH_ 64
#define F_  4096
#define E_  8
#define K_  2
#define B_  2
#define S_  2048
#define N_  (B_ * S_)          // 4096 tokens
#define BH_ (B_ * H_)          // 32
#define ND_ ((long)N_ * D_)    // 4194304

// ---------------- scratch (device globals; no allocation allowed) -------------
__device__ float g_q[N_ * D_];
__device__ float g_k[N_ * D_];
__device__ float g_v[N_ * D_];
__device__ float g_attn[N_ * D_];
__device__ float g_t[N_ * D_];
__device__ float g_x1[N_ * D_];
__device__ float g_x2[N_ * D_];
__device__ float g_s[(long)N_ * K_ * F_];   // MoE hidden (128MB)
__device__ float g_y[(long)N_ * K_ * D_];   // MoE expert outputs per dispatch row

__device__ int   g_topi[N_ * K_];
__device__ float g_gate[N_ * K_];
__device__ int   g_drow[N_ * K_];           // token -> its dispatch rows
__device__ int   g_cnt[E_];
__device__ int   g_off[E_];
__device__ int   g_cur[E_];
__device__ int   g_dtok[N_ * K_];
__device__ float g_probs[N_ * E_];
__device__ int   g_loadcnt[E_];

// ---------------- mma / cp.async / ldmatrix helpers ----------------------------
__device__ __forceinline__ void mma_tf32(float* c, const uint32_t* a, const uint32_t* b)
{
    asm volatile(
        "mma.sync.aligned.m16n8k8.row.col.f32.tf32.tf32.f32 "
        "{%0,%1,%2,%3}, {%4,%5,%6,%7}, {%8,%9}, {%0,%1,%2,%3};\n"
        : "+f"(c[0]), "+f"(c[1]), "+f"(c[2]), "+f"(c[3])
        : "r"(a[0]), "r"(a[1]), "r"(a[2]), "r"(a[3]), "r"(b[0]), "r"(b[1]));
}

__device__ __forceinline__ void ldsm4(uint32_t* r, uint32_t addr)
{
    asm volatile("ldmatrix.sync.aligned.m8n8.x4.shared.b16 {%0,%1,%2,%3}, [%4];\n"
                 : "=r"(r[0]), "=r"(r[1]), "=r"(r[2]), "=r"(r[3]) : "r"(addr));
}

__device__ __forceinline__ void ldsm2(uint32_t* r, uint32_t addr)
{
    asm volatile("ldmatrix.sync.aligned.m8n8.x2.shared.b16 {%0,%1}, [%2];\n"
                 : "=r"(r[0]), "=r"(r[1]) : "r"(addr));
}

__device__ __forceinline__ void cp16(uint32_t dst, const void* src, int srcbytes)
{
    asm volatile("cp.async.cg.shared.global [%0], [%1], 16, %2;\n"
                 :: "r"(dst), "l"(src), "r"(srcbytes));
}
#define CP_COMMIT asm volatile("cp.async.commit_group;\n")
#define CP_WAIT1  asm volatile("cp.async.wait_group 1;\n")
#define CP_WAIT0  asm volatile("cp.async.wait_group 0;\n")

// ---------------- 3-stage pipelined tf32 GEMM core (128x128 tile, TBK=16) ------
// 256 threads, 8 warps in 2(M)x4(N), warp tile 64x32.
// Ring of 3 smem stages; prefetch stage k+2 issued at iter k -> each load has
// ~2 compute iterations of slack; wait_group 1 only requires the OLDER of two
// in-flight groups to be complete.
// A smem row-major stride 20 words, B stride 136 (both conflict-free).
// Dynamic smem: 3*(128*20 + 16*136)*4 = 56832 B -> 2 CTAs/SM.
#define TBK 16
#define AST 20
#define BST 136
#define A_STG (128 * AST)
#define B_STG (TBK * BST)
#define GEMM_SMEM_BYTES ((3 * A_STG + 3 * B_STG) * 4)   // 56832

template<bool GATHER, bool RELU>
__device__ __forceinline__ void gemm128_db(
    const float* __restrict__ A, int lda,
    const float* __restrict__ B, int ldb,
    float* __restrict__ C, int ldc,
    int M, int K, int n0,
    const float* __restrict__ bias,
    const int* __restrict__ gidx)
{
    extern __shared__ float smg[];
    float* As = smg;
    float* Bs = smg + 3 * A_STG;

    const int tid = threadIdx.x;
    const int m0 = blockIdx.y * 128;
    if (m0 >= M) return;

    const int w = tid >> 5;
    const int lane = tid & 31;
    const int gid = lane >> 2;
    const int tig = lane & 3;
    const int wm = (w & 1) * 64;
    const int wn = (w >> 1) * 32;

    float acc[4][4][4];
#pragma unroll
    for (int mi = 0; mi < 4; mi++)
#pragma unroll
        for (int ni = 0; ni < 4; ni++)
#pragma unroll
            for (int r = 0; r < 4; r++) acc[mi][ni][r] = 0.f;

    // A loader: row = tid>>1 (128 rows), 8 floats starting at (tid&1)*8
    const int ar = tid >> 1;
    const int ac = (tid & 1) * 8;
    const bool avalid = (m0 + ar) < M;
    long grow = 0;
    if (avalid) grow = GATHER ? (long)gidx[m0 + ar] : (long)(m0 + ar);
    const float* Ap = A + grow * (long)lda + ac;
    const int ab = avalid ? 16 : 0;

    // B loader: row = tid>>4 (16 rows), 8 floats at (tid&15)*8
    const int br = tid >> 4;
    const int bc = (tid & 15) * 8;
    const float* Bp = B + (long)br * ldb + n0 + bc;

    uint32_t adst[3], bdst[3], albase[3];
    const int rowoff = lane & 15;
    const int coloff = (lane >> 4) * 4;
#pragma unroll
    for (int st = 0; st < 3; st++) {
        adst[st] = (uint32_t)__cvta_generic_to_shared(&As[st * A_STG + ar * AST + ac]);
        bdst[st] = (uint32_t)__cvta_generic_to_shared(&Bs[st * B_STG + br * BST + bc]);
        albase[st] = (uint32_t)__cvta_generic_to_shared(
            &As[st * A_STG + (wm + rowoff) * AST + coloff]);
    }

    const int KT = K / TBK;

    // prologue: stages 0 and 1 (two groups in flight)
    {
        cp16(adst[0], Ap, ab);
        cp16(adst[0] + 16, Ap + 4, ab);
        cp16(bdst[0], Bp, 16);
        cp16(bdst[0] + 16, Bp + 4, 16);
        CP_COMMIT;
        if (1 < KT) {
            const float* ap = Ap + TBK;
            const float* bp = Bp + (long)TBK * ldb;
            cp16(adst[1], ap, ab);
            cp16(adst[1] + 16, ap + 4, ab);
            cp16(bdst[1], bp, 16);
            cp16(bdst[1] + 16, bp + 4, 16);
            CP_COMMIT;
        }
    }

    int cur = 0, nxt2 = 2;
    for (int kt = 0; kt < KT; kt++) {
        if (kt + 1 < KT) { CP_WAIT1; } else { CP_WAIT0; }
        __syncthreads();
        if (kt + 2 < KT) {
            const float* ap = Ap + (kt + 2) * TBK;
            const float* bp = Bp + (long)(kt + 2) * TBK * ldb;
            cp16(adst[nxt2], ap, ab);
            cp16(adst[nxt2] + 16, ap + 4, ab);
            cp16(bdst[nxt2], bp, 16);
            cp16(bdst[nxt2] + 16, bp + 4, 16);
            CP_COMMIT;
        }

        const float* bs = Bs + cur * B_STG;
        const uint32_t alb = albase[cur];
#pragma unroll
        for (int ks = 0; ks < TBK; ks += 8) {
            uint32_t af[4][4], bf[4][2];
#pragma unroll
            for (int mi = 0; mi < 4; mi++)
                ldsm4(af[mi], alb + (mi * 16 * AST + ks) * 4);
#pragma unroll
            for (int ni = 0; ni < 4; ni++) {
                const int ncol = wn + ni * 8 + gid;
                bf[ni][0] = __float_as_uint(bs[(ks + tig) * BST + ncol]);
                bf[ni][1] = __float_as_uint(bs[(ks + tig + 4) * BST + ncol]);
            }
#pragma unroll
            for (int mi = 0; mi < 4; mi++)
#pragma unroll
                for (int ni = 0; ni < 4; ni++)
                    mma_tf32(acc[mi][ni], af[mi], bf[ni]);
        }
        cur = (cur == 2) ? 0 : cur + 1;
        nxt2 = (nxt2 == 2) ? 0 : nxt2 + 1;
    }

    // epilogue (c0:(r,c) c1:(r,c+1) c2:(r+8,c) c3:(r+8,c+1))
#pragma unroll
    for (int mi = 0; mi < 4; mi++) {
#pragma unroll
        for (int half = 0; half < 2; half++) {
            const int row = m0 + wm + mi * 16 + gid + half * 8;
            if (row >= M) continue;
            float* cp = C + (long)row * ldc;
#pragma unroll
            for (int ni = 0; ni < 4; ni++) {
                const int col = n0 + wn + ni * 8 + tig * 2;
                float v0 = acc[mi][ni][half * 2 + 0];
                float v1 = acc[mi][ni][half * 2 + 1];
                if (bias) { v0 += bias[col]; v1 += bias[col + 1]; }
                if constexpr (RELU) { v0 = fmaxf(v0, 0.f); v1 = fmaxf(v1, 0.f); }
                *(float2*)(cp + col) = make_float2(v0, v1);
            }
        }
    }
}

// ---------------- GEMM wrappers -------------------------------------------------
__global__ void __launch_bounds__(256) k_proj3(
    const float* a0, const float* a1, const float* a2,
    const float* w0, const float* w1, const float* w2,
    const float* bi0, const float* bi1, const float* bi2,
    float* c0, float* c1, float* c2)
{
    const float *A, *W, *bi;
    float* C;
    if (blockIdx.z == 0)      { A = a0; W = w0; bi = bi0; C = c0; }
    else if (blockIdx.z == 1) { A = a1; W = w1; bi = bi1; C = c1; }
    else                      { A = a2; W = w2; bi = bi2; C = c2; }
    gemm128_db<false, false>(A, D_, W, D_, C, D_, N_, D_, blockIdx.x * 128,
                             bi, nullptr);
}

__global__ void __launch_bounds__(256) k_proj1(
    const float* __restrict__ A, const float* __restrict__ W,
    const float* __restrict__ bi, float* __restrict__ C)
{
    gemm128_db<false, false>(A, D_, W, D_, C, D_, N_, D_, blockIdx.x * 128,
                             bi, nullptr);
}

// MoE FF1: h = relu(gather(x2) @ W1[e] + b1[e]) into g_s
__global__ void __launch_bounds__(256) k_ff1(
    const float* __restrict__ W1, const float* __restrict__ B1)
{
    const int e = blockIdx.z;
    const int cnt = g_cnt[e];
    if ((int)(blockIdx.y * 128) >= cnt) return;
    const int off = g_off[e];
    gemm128_db<true, true>(
        g_x2, D_, W1 + (long)e * D_ * F_, F_,
        g_s + (long)off * F_, F_,
        cnt, D_, blockIdx.x * 128, B1 + (long)e * F_,
        g_dtok + off);
}

// MoE FF2: y[dispatch_row] = h @ W2[e] + b2[e]   (plain stores)
__global__ void __launch_bounds__(256) k_ff2(
    const float* __restrict__ W2, const float* __restrict__ B2)
{
    const int e = blockIdx.z;
    const int cnt = g_cnt[e];
    if ((int)(blockIdx.y * 128) >= cnt) return;
    const int off = g_off[e];
    gemm128_db<false, false>(
        g_s + (long)off * F_, F_, W2 + (long)e * F_ * D_, D_,
        g_y + (long)off * D_, D_,
        cnt, F_, blockIdx.x * 128, B2 + (long)e * D_,
        nullptr);
}

// ---------------- flash attention (single-buffer K/V, 105KB -> 2 CTAs/SM) ------
#define QS_OFF 0
#define PS_OFF 8704
#define KS_OFF 17408
#define VS_OFF 21760
#define FL_SMEM_WORDS 26368   // *4 = 105472 bytes

__global__ void __launch_bounds__(256) k_flash()
{
    extern __shared__ float sm[];
#define QS(r, c) sm[QS_OFF + (r) * 68 + (c)]
#define PS(r, c) sm[PS_OFF + (r) * 68 + (c)]
#define KS(r, c) sm[KS_OFF + (r) * 68 + (c)]
#define VS(r, c) sm[VS_OFF + (r) * 72 + (c)]

    const int tid = threadIdx.x;
    const int w = tid >> 5;
    const int lane = tid & 31;
    const int gid = lane >> 2;
    const int tig = lane & 3;
    const int wm = w * 16;

    const int qb = blockIdx.x;
    const int z = blockIdx.y;
    const int b = z >> 4, h = z & 15;
    const int q0 = qb * 128;

    // ldmatrix lane-addresses
    const int rowoff = lane & 15;
    const int coloff = (lane >> 4) * 4;
    const uint32_t qlb = (uint32_t)__cvta_generic_to_shared(
        &QS(wm + rowoff, coloff));
    const uint32_t plb = (uint32_t)__cvta_generic_to_shared(
        &PS(wm + rowoff, coloff));
    const int krow = lane & 7;
    const int kcol = ((lane >> 3) & 1) * 4;
    const uint32_t klb = (uint32_t)__cvta_generic_to_shared(&KS(krow, kcol));

    // Q tile (128 x 64)
    {
        const int r = tid >> 1;
        const int c0 = (tid & 1) * 32;
        const float* qp = g_q + ((long)(b * S_ + q0 + r)) * D_ + h * DH_ + c0;
        uint32_t qd = (uint32_t)__cvta_generic_to_shared(&QS(r, c0));
#pragma unroll
        for (int i = 0; i < 8; i++) cp16(qd + i * 16, qp + i * 4, 16);
    }

    const int ls = tid >> 2;
    const int ld0 = (tid & 3) * 16;
    const long kvb = ((long)(b * S_ + ls)) * D_ + h * DH_ + ld0;
    uint32_t kd = (uint32_t)__cvta_generic_to_shared(&KS(ls, ld0));
    uint32_t vd = (uint32_t)__cvta_generic_to_shared(&VS(ls, ld0));

    {
        const float* kp = g_k + kvb;
        const float* vp = g_v + kvb;
#pragma unroll
        for (int i = 0; i < 4; i++) {
            cp16(kd + i * 16, kp + i * 4, 16);
            cp16(vd + i * 16, vp + i * 4, 16);
        }
    }
    CP_COMMIT;

    float m0v = -3.4e38f, m1v = -3.4e38f;
    float l0 = 0.f, l1 = 0.f;
    float o[8][4];
#pragma unroll
    for (int ni = 0; ni < 8; ni++)
#pragma unroll
        for (int r = 0; r < 4; r++) o[ni][r] = 0.f;

    const int J = S_ / 64;
    for (int j = 0; j < J; j++) {
        CP_WAIT0;
        __syncthreads();

        // S = Q @ K^T (warp: 16 rows x 64 keys), then * 0.125
        float sacc[8][4];
#pragma unroll
        for (int ni = 0; ni < 8; ni++)
#pragma unroll
            for (int r = 0; r < 4; r++) sacc[ni][r] = 0.f;
#pragma unroll
        for (int ks = 0; ks < 64; ks += 8) {
            uint32_t af[4];
            ldsm4(af, qlb + ks * 4);
#pragma unroll
            for (int ni = 0; ni < 8; ni++) {
                uint32_t bf[2];
                ldsm2(bf, klb + (ni * 8 * 68 + ks) * 4);
                mma_tf32(sacc[ni], af, bf);
            }
        }
#pragma unroll
        for (int ni = 0; ni < 8; ni++)
#pragma unroll
            for (int r = 0; r < 4; r++) sacc[ni][r] *= 0.125f;

        // online softmax
        float mx0 = -3.4e38f, mx1 = -3.4e38f;
#pragma unroll
        for (int ni = 0; ni < 8; ni++) {
            mx0 = fmaxf(mx0, fmaxf(sacc[ni][0], sacc[ni][1]));
            mx1 = fmaxf(mx1, fmaxf(sacc[ni][2], sacc[ni][3]));
        }
        mx0 = fmaxf(mx0, __shfl_xor_sync(0xffffffffu, mx0, 1));
        mx0 = fmaxf(mx0, __shfl_xor_sync(0xffffffffu, mx0, 2));
        mx1 = fmaxf(mx1, __shfl_xor_sync(0xffffffffu, mx1, 1));
        mx1 = fmaxf(mx1, __shfl_xor_sync(0xffffffffu, mx1, 2));
        const float mn0 = fmaxf(m0v, mx0);
        const float mn1 = fmaxf(m1v, mx1);
        const float a0 = __expf(m0v - mn0);
        const float a1 = __expf(m1v - mn1);
        m0v = mn0; m1v = mn1;

        float s0 = 0.f, s1 = 0.f;
#pragma unroll
        for (int ni = 0; ni < 8; ni++) {
            float p0 = __expf(sacc[ni][0] - mn0);
            float p1 = __expf(sacc[ni][1] - mn0);
            float p2 = __expf(sacc[ni][2] - mn1);
            float p3 = __expf(sacc[ni][3] - mn1);
            s0 += p0 + p1; s1 += p2 + p3;
            const int col = ni * 8 + tig * 2;
            PS(wm + gid, col) = p0;
            PS(wm + gid, col + 1) = p1;
            PS(wm + gid + 8, col) = p2;
            PS(wm + gid + 8, col + 1) = p3;
        }
        s0 += __shfl_xor_sync(0xffffffffu, s0, 1);
        s0 += __shfl_xor_sync(0xffffffffu, s0, 2);
        s1 += __shfl_xor_sync(0xffffffffu, s1, 1);
        s1 += __shfl_xor_sync(0xffffffffu, s1, 2);
        l0 = l0 * a0 + s0;
        l1 = l1 * a1 + s1;

#pragma unroll
        for (int ni = 0; ni < 8; ni++) {
            o[ni][0] *= a0; o[ni][1] *= a0;
            o[ni][2] *= a1; o[ni][3] *= a1;
        }
        __syncwarp();

        // O += P @ V
#pragma unroll
        for (int ks = 0; ks < 64; ks += 8) {
            uint32_t af[4];
            ldsm4(af, plb + ks * 4);
#pragma unroll
            for (int ni = 0; ni < 8; ni++) {
                uint32_t bf[2];
                bf[0] = __float_as_uint(VS(ks + tig, ni * 8 + gid));
                bf[1] = __float_as_uint(VS(ks + tig + 4, ni * 8 + gid));
                mma_tf32(o[ni], af, bf);
            }
        }
        __syncthreads();

        if (j + 1 < J) {
            const float* kp = g_k + kvb + (long)(j + 1) * 64 * D_;
            const float* vp = g_v + kvb + (long)(j + 1) * 64 * D_;
#pragma unroll
            for (int i = 0; i < 4; i++) {
                cp16(kd + i * 16, kp + i * 4, 16);
                cp16(vd + i * 16, vp + i * 4, 16);
            }
            CP_COMMIT;
        }
    }

    // write O (normalized)
    const float inv0 = 1.f / l0;
    const float inv1 = 1.f / l1;
    const long r0 = (long)(b * S_ + q0 + wm + gid) * D_ + h * DH_;
    const long r1 = r0 + 8 * D_;
#pragma unroll
    for (int ni = 0; ni < 8; ni++) {
        const int col = ni * 8 + tig * 2;
        *(float2*)(g_attn + r0 + col) = make_float2(o[ni][0] * inv0, o[ni][1] * inv0);
        *(float2*)(g_attn + r1 + col) = make_float2(o[ni][2] * inv1, o[ni][3] * inv1);
    }
#undef QS
#undef PS
#undef KS
#undef VS
}

// ---------------- elementwise / LN ---------------------------------------------
__global__ void k_zero()
{
    int i = threadIdx.x;
    if (i < E_) { g_cnt[i] = 0; g_cur[i] = 0; g_loadcnt[i] = 0; }
}

__global__ void k_addln(const float* __restrict__ a, const float* __restrict__ b,
                        const float* __restrict__ g, const float* __restrict__ be,
                        float* __restrict__ out)
{
    __shared__ float buf[D_];
    __shared__ float red[256];
    const int t = blockIdx.x;
    const int tid = threadIdx.x;
    const float* pa = a + (long)t * D_;
    const float* pb = b + (long)t * D_;
    float s = 0.f;
    for (int i = tid; i < D_; i += 256) { float v = pa[i] + pb[i]; buf[i] = v; s += v; }
    red[tid] = s; __syncthreads();
    for (int o = 128; o > 0; o >>= 1) { if (tid < o) red[tid] += red[tid + o]; __syncthreads(); }
    float mean = red[0] * (1.f / D_);
    __syncthreads();
    float vs = 0.f;
    for (int i = tid; i < D_; i += 256) { float d = buf[i] - mean; vs += d * d; }
    red[tid] = vs; __syncthreads();
    for (int o = 128; o > 0; o >>= 1) { if (tid < o) red[tid] += red[tid + o]; __syncthreads(); }
    float rstd = rsqrtf(red[0] * (1.f / D_) + 1e-5f);
    float* po = out + (long)t * D_;
    for (int i = tid; i < D_; i += 256)
        po[i] = (buf[i] - mean) * rstd * g[i] + be[i];
}

// final LN fused with MoE combine: out = LN(x2 + g0*y[d0] + g1*y[d1])
__global__ void k_addln_moe(const float* __restrict__ a,
                            const float* __restrict__ g, const float* __restrict__ be,
                            float* __restrict__ out)
{
    __shared__ float buf[D_];
    __shared__ float red[256];
    const int t = blockIdx.x;
    const int tid = threadIdx.x;
    const float* pa = a + (long)t * D_;
    const float* y0 = g_y + (long)g_drow[t * 2] * D_;
    const float* y1 = g_y + (long)g_drow[t * 2 + 1] * D_;
    const float gt0 = g_gate[t * 2];
    const float gt1 = g_gate[t * 2 + 1];
    float s = 0.f;
    for (int i = tid; i < D_; i += 256) {
        float v = pa[i] + gt0 * y0[i] + gt1 * y1[i];
        buf[i] = v; s += v;
    }
    red[tid] = s; __syncthreads();
    for (int o = 128; o > 0; o >>= 1) { if (tid < o) red[tid] += red[tid + o]; __syncthreads(); }
    float mean = red[0] * (1.f / D_);
    __syncthreads();
    float vs = 0.f;
    for (int i = tid; i < D_; i += 256) { float d = buf[i] - mean; vs += d * d; }
    red[tid] = vs; __syncthreads();
    for (int o = 128; o > 0; o >>= 1) { if (tid < o) red[tid] += red[tid + o]; __syncthreads(); }
    float rstd = rsqrtf(red[0] * (1.f / D_) + 1e-5f);
    float* po = out + (long)t * D_;
    for (int i = tid; i < D_; i += 256)
        po[i] = (buf[i] - mean) * rstd * g[i] + be[i];
}

// ---------------- router / dispatch / aux --------------------------------------
__device__ __forceinline__ void router_core(const float* __restrict__ x,
                                            const float* __restrict__ rw,
                                            const float* __restrict__ rb,
                                            int lane, float* probs_out,
                                            int* i1_out, int* i2_out)
{
    float le[E_];
#pragma unroll
    for (int e = 0; e < E_; e++) le[e] = 0.f;
    for (int d0 = lane * 4; d0 < D_; d0 += 128) {
        float4 xv = *(const float4*)(x + d0);
        float xa[4] = {xv.x, xv.y, xv.z, xv.w};
#pragma unroll
        for (int r = 0; r < 4; r++) {
            const float* w = rw + (long)(d0 + r) * E_;
            float4 w0 = *(const float4*)(w);
            float4 w1 = *(const float4*)(w + 4);
            le[0] = fmaf(xa[r], w0.x, le[0]); le[1] = fmaf(xa[r], w0.y, le[1]);
            le[2] = fmaf(xa[r], w0.z, le[2]); le[3] = fmaf(xa[r], w0.w, le[3]);
            le[4] = fmaf(xa[r], w1.x, le[4]); le[5] = fmaf(xa[r], w1.y, le[5]);
            le[6] = fmaf(xa[r], w1.z, le[6]); le[7] = fmaf(xa[r], w1.w, le[7]);
        }
    }
#pragma unroll
    for (int e = 0; e < E_; e++)
        for (int o = 16; o > 0; o >>= 1) le[e] += __shfl_xor_sync(0xffffffffu, le[e], o);
    float mx = -3.4e38f;
#pragma unroll
    for (int e = 0; e < E_; e++) { le[e] += rb[e]; mx = fmaxf(mx, le[e]); }
    float sum = 0.f;
#pragma unroll
    for (int e = 0; e < E_; e++) { le[e] = expf(le[e] - mx); sum += le[e]; }
    float inv = 1.f / sum;
#pragma unroll
    for (int e = 0; e < E_; e++) { le[e] *= inv; probs_out[e] = le[e]; }
    int i1 = 0;
    for (int e = 1; e < E_; e++) if (le[e] > le[i1]) i1 = e;
    int i2 = (i1 == 0) ? 1 : 0;
    for (int e = 0; e < E_; e++) if (e != i1 && le[e] > le[i2]) i2 = e;
    *i1_out = i1; *i2_out = i2;
}

__global__ void k_router(const float* __restrict__ rw, const float* __restrict__ rb)
{
    const int warp = threadIdx.x >> 5, lane = threadIdx.x & 31;
    const int t = blockIdx.x * 8 + warp;
    if (t >= N_) return;
    float probs[E_]; int i1, i2;
    router_core(g_x2 + (long)t * D_, rw, rb, lane, probs, &i1, &i2);
    if (lane == 0) {
        float gs = probs[i1] + probs[i2];
        g_topi[t * 2] = i1; g_topi[t * 2 + 1] = i2;
        g_gate[t * 2] = probs[i1] / gs; g_gate[t * 2 + 1] = probs[i2] / gs;
        atomicAdd(&g_cnt[i1], 1); atomicAdd(&g_cnt[i2], 1);
    }
}

__global__ void k_scan()
{
    if (threadIdx.x == 0) {
        int s = 0;
        for (int e = 0; e < E_; e++) { g_off[e] = s; s += g_cnt[e]; }
    }
}

__global__ void k_fill()
{
    int t = blockIdx.x * 256 + threadIdx.x;
    if (t >= N_) return;
#pragma unroll
    for (int k = 0; k < K_; k++) {
        int e = g_topi[t * K_ + k];
        int p = atomicAdd(&g_cur[e], 1);
        int d = g_off[e] + p;
        g_dtok[d] = t;
        g_drow[t * K_ + k] = d;
    }
}

__global__ void k_aux_router(const float* __restrict__ X,
                             const float* __restrict__ rw, const float* __restrict__ rb)
{
    const int warp = threadIdx.x >> 5, lane = threadIdx.x & 31;
    const int t = blockIdx.x * 8 + warp;
    if (t >= N_) return;
    float probs[E_]; int i1, i2;
    router_core(X + (long)t * D_, rw, rb, lane, probs, &i1, &i2);
    if (lane == 0) {
#pragma unroll
        for (int e = 0; e < E_; e++) g_probs[t * E_ + e] = probs[e];
        atomicAdd(&g_loadcnt[i1], 1); atomicAdd(&g_loadcnt[i2], 1);
    }
}

__global__ void k_aux_reduce(float* __restrict__ out, int write)
{
    __shared__ float red[256];
    const int tid = threadIdx.x;
    float imp[E_];
#pragma unroll
    for (int e = 0; e < E_; e++) imp[e] = 0.f;
    for (int t = tid; t < N_; t += 256)
#pragma unroll
        for (int e = 0; e < E_; e++) imp[e] += g_probs[t * E_ + e];
    float aux = 0.f;
    for (int e = 0; e < E_; e++) {
        red[tid] = imp[e]; __syncthreads();
        for (int o = 128; o > 0; o >>= 1) { if (tid < o) red[tid] += red[tid + o]; __syncthreads(); }
        if (tid == 0)
            aux += (red[0] / (float)N_) * ((float)g_loadcnt[e] / (float)(N_ * K_));
        __syncthreads();
    }
    if (tid == 0 && write) out[ND_] = aux * (float)E_;
}

// ---------------- launch ------------------------------------------------------
extern "C" void kernel_launch(void* const* d_in, const int* in_sizes, int n_in,
                              void* d_out, int out_size)
{
    (void)in_sizes; (void)n_in;
    const float* x     = (const float*)d_in[0];
    const float* enc   = (const float*)d_in[1];
    const float* sa_wq = (const float*)d_in[2];
    const float* sa_bq = (const float*)d_in[3];
    const float* sa_wk = (const float*)d_in[4];
    const float* sa_bk = (const float*)d_in[5];
    const float* sa_wv = (const float*)d_in[6];
    const float* sa_bv = (const float*)d_in[7];
    const float* sa_wo = (const float*)d_in[8];
    const float* sa_bo = (const float*)d_in[9];
    const float* ca_wq = (const float*)d_in[10];
    const float* ca_bq = (const float*)d_in[11];
    const float* ca_wk = (const float*)d_in[12];
    const float* ca_bk = (const float*)d_in[13];
    const float* ca_wv = (const float*)d_in[14];
    const float* ca_bv = (const float*)d_in[15];
    const float* ca_wo = (const float*)d_in[16];
    const float* ca_bo = (const float*)d_in[17];
    const float* n1_g  = (const float*)d_in[18];
    const float* n1_b  = (const float*)d_in[19];
    const float* n2_g  = (const float*)d_in[20];
    const float* n2_b  = (const float*)d_in[21];
    const float* n3_g  = (const float*)d_in[22];
    const float* n3_b  = (const float*)d_in[23];
    const float* r_w   = (const float*)d_in[24];
    const float* r_b   = (const float*)d_in[25];
    const float* e_w1  = (const float*)d_in[26];
    const float* e_b1  = (const float*)d_in[27];
    const float* e_w2  = (const float*)d_in[28];
    const float* e_b2  = (const float*)d_in[29];
    float* out = (float*)d_out;

    float *pq, *pk, *pv, *pattn, *pt, *px1, *px2;
    cudaGetSymbolAddress((void**)&pq, g_q);
    cudaGetSymbolAddress((void**)&pk, g_k);
    cudaGetSymbolAddress((void**)&pv, g_v);
    cudaGetSymbolAddress((void**)&pattn, g_attn);
    cudaGetSymbolAddress((void**)&pt, g_t);
    cudaGetSymbolAddress((void**)&px1, g_x1);
    cudaGetSymbolAddress((void**)&px2, g_x2);

    static int s_attr_done = 0;
    if (!s_attr_done) {
        cudaFuncSetAttribute(k_flash, cudaFuncAttributeMaxDynamicSharedMemorySize,
                             FL_SMEM_WORDS * 4);
        cudaFuncSetAttribute(k_proj3, cudaFuncAttributeMaxDynamicSharedMemorySize,
                             GEMM_SMEM_BYTES);
        cudaFuncSetAttribute(k_proj1, cudaFuncAttributeMaxDynamicSharedMemorySize,
                             GEMM_SMEM_BYTES);
        cudaFuncSetAttribute(k_ff1, cudaFuncAttributeMaxDynamicSharedMemorySize,
                             GEMM_SMEM_BYTES);
        cudaFuncSetAttribute(k_ff2, cudaFuncAttributeMaxDynamicSharedMemorySize,
                             GEMM_SMEM_BYTES);
        s_attr_done = 1;
    }

    dim3 blk(256);
    dim3 gP3(D_ / 128, N_ / 128, 3);           // (8, 32, 3)
    dim3 gP1(D_ / 128, N_ / 128);              // (8, 32)
    dim3 gFlash(S_ / 128, BH_);                // (16, 32)

    k_zero<<<1, 32>>>();

    // ---- self attention ----
    k_proj3<<<gP3, blk, GEMM_SMEM_BYTES>>>(x, x, x, sa_wq, sa_wk, sa_wv,
                                           sa_bq, sa_bk, sa_bv, pq, pk, pv);
    k_flash<<<gFlash, blk, FL_SMEM_WORDS * 4>>>();
    k_proj1<<<gP1, blk, GEMM_SMEM_BYTES>>>(pattn, sa_wo, sa_bo, pt);
    k_addln<<<N_, blk>>>(x, pt, n1_g, n1_b, px1);

    // ---- cross attention ----
    k_proj3<<<gP3, blk, GEMM_SMEM_BYTES>>>(px1, enc, enc, ca_wq, ca_wk, ca_wv,
                                           ca_bq, ca_bk, ca_bv, pq, pk, pv);
    k_flash<<<gFlash, blk, FL_SMEM_WORDS * 4>>>();
    k_proj1<<<gP1, blk, GEMM_SMEM_BYTES>>>(pattn, ca_wo, ca_bo, pt);
    k_addln<<<N_, blk>>>(px1, pt, n2_g, n2_b, px2);

    // ---- MoE (sparse top-2 dispatch, no atomic combine) ----
    k_router<<<N_ / 8, blk>>>(r_w, r_b);
    k_scan<<<1, 32>>>();
    k_fill<<<N_ / 256, blk>>>();
    k_ff1<<<dim3(F_ / 128, 64, E_), blk, GEMM_SMEM_BYTES>>>(e_w1, e_b1);
    k_ff2<<<dim3(D_ / 128, 64, E_), blk, GEMM_SMEM_BYTES>>>(e_w2, e_b2);
    k_addln_moe<<<N_, blk>>>(px2, n3_g, n3_b, out);

    // ---- aux loss on final output ----
    k_aux_router<<<N_ / 8, blk>>>(out, r_w, r_b);
    k_aux_reduce<<<1, blk>>>(out, ((long)out_size > ND_) ? 1 : 0);
}

// round 17
// speedup vs baseline: 1.4435x; 1.3329x over previous
#include <cuda_runtime.h>
#include <cuda_fp16.h>
#include <math.h>
#include <stdint.h>

#define D_  1024
#define H_  16
#define DH_ 64
#define F_  4096
#define E_  8
#define K_  2
#define B_  2
#define S_  2048
#define N_  (B_ * S_)          // 4096 tokens
#define BH_ (B_ * H_)          // 32
#define ND_ ((long)N_ * D_)    // 4194304

// ---------------- scratch (device globals; no allocation allowed) -------------
__device__ float  g_q[N_ * D_];
__device__ float  g_k[N_ * D_];
__device__ float  g_v[N_ * D_];
__device__ float  g_t[N_ * D_];
__device__ float  g_x1[N_ * D_];
__device__ float  g_x2[N_ * D_];
__device__ float  g_y[(long)N_ * K_ * D_];     // MoE expert outputs (fp32)

__device__ __half g_xh[N_ * D_];               // fp16 activations
__device__ __half g_ench[N_ * D_];
__device__ __half g_attnh[N_ * D_];
__device__ __half g_x1h[N_ * D_];
__device__ __half g_x2h[N_ * D_];
__device__ __half g_sh[(long)N_ * K_ * F_];    // MoE hidden (fp16, 64MB)

__device__ __half g_wth[8][D_ * D_];           // proj weights^T fp16 (16MB)
__device__ __half g_w1th[(long)E_ * F_ * D_];  // W1^T fp16 (64MB)
__device__ __half g_w2th[(long)E_ * D_ * F_];  // W2^T fp16 (64MB)

__device__ int   g_topi[N_ * K_];
__device__ float g_gate[N_ * K_];
__device__ int   g_drow[N_ * K_];
__device__ int   g_cnt[E_];
__device__ int   g_off[E_];
__device__ int   g_cur[E_];
__device__ int   g_dtok[N_ * K_];
__device__ float g_probs[N_ * E_];
__device__ int   g_loadcnt[E_];

// ---------------- mma / cp.async / ldmatrix helpers ----------------------------
__device__ __forceinline__ void mma_tf32(float* c, const uint32_t* a, const uint32_t* b)
{
    asm volatile(
        "mma.sync.aligned.m16n8k8.row.col.f32.tf32.tf32.f32 "
        "{%0,%1,%2,%3}, {%4,%5,%6,%7}, {%8,%9}, {%0,%1,%2,%3};\n"
        : "+f"(c[0]), "+f"(c[1]), "+f"(c[2]), "+f"(c[3])
        : "r"(a[0]), "r"(a[1]), "r"(a[2]), "r"(a[3]), "r"(b[0]), "r"(b[1]));
}

__device__ __forceinline__ void mma_f16(float* c, const uint32_t* a, const uint32_t* b)
{
    asm volatile(
        "mma.sync.aligned.m16n8k16.row.col.f32.f16.f16.f32 "
        "{%0,%1,%2,%3}, {%4,%5,%6,%7}, {%8,%9}, {%0,%1,%2,%3};\n"
        : "+f"(c[0]), "+f"(c[1]), "+f"(c[2]), "+f"(c[3])
        : "r"(a[0]), "r"(a[1]), "r"(a[2]), "r"(a[3]), "r"(b[0]), "r"(b[1]));
}

__device__ __forceinline__ void ldsm4(uint32_t* r, uint32_t addr)
{
    asm volatile("ldmatrix.sync.aligned.m8n8.x4.shared.b16 {%0,%1,%2,%3}, [%4];\n"
                 : "=r"(r[0]), "=r"(r[1]), "=r"(r[2]), "=r"(r[3]) : "r"(addr));
}

__device__ __forceinline__ void ldsm2(uint32_t* r, uint32_t addr)
{
    asm volatile("ldmatrix.sync.aligned.m8n8.x2.shared.b16 {%0,%1}, [%2];\n"
                 : "=r"(r[0]), "=r"(r[1]) : "r"(addr));
}

__device__ __forceinline__ void cp16(uint32_t dst, const void* src, int srcbytes)
{
    asm volatile("cp.async.cg.shared.global [%0], [%1], 16, %2;\n"
                 :: "r"(dst), "l"(src), "r"(srcbytes));
}
#define CP_COMMIT asm volatile("cp.async.commit_group;\n")
#define CP_WAIT0  asm volatile("cp.async.wait_group 0;\n")

// ---------------- fp16 tensor-core GEMM core (128x128 tile, 32 halves/stage) ---
// 256 threads, 8 warps 2(M)x4(N), warp tile 64x32. mma m16n8k16 f16->f32.
// A [M][K] fp16 row-major; BT [Nout][K] fp16 row-major (pre-transposed weights).
// Smem rows padded to 40 halves (80B = 20 words): ldsm row phases and the
// B half2 loads both hit 32 distinct banks. Static smem 40KB -> 2 CTAs/SM.
// Pipeline identical to the proven round-6 cadence: wait0 -> sync -> prefetch
// next stage -> compute current.
#define HST 40
#define H_ASTG (128 * HST)

// WMODE: 0 = fp32 C, 2 = fp16 C
template<int WMODE, bool GATHER, bool RELU>
__device__ __forceinline__ void hgemm(
    const __half* __restrict__ A, int lda,
    const __half* __restrict__ BT, int ldb,
    float* __restrict__ C, __half* __restrict__ Ch, int ldc,
    int M, int Kdim, int n0,
    const float* __restrict__ bias,
    const int* __restrict__ gidx)
{
    __shared__ __half As[2][H_ASTG];
    __shared__ __half Bs[2][H_ASTG];

    const int tid = threadIdx.x;
    const int m0 = blockIdx.y * 128;
    if (m0 >= M) return;

    const int w = tid >> 5;
    const int lane = tid & 31;
    const int gid = lane >> 2;
    const int tig = lane & 3;
    const int wm = (w & 1) * 64;
    const int wn = (w >> 1) * 32;

    float acc[4][4][4];
#pragma unroll
    for (int mi = 0; mi < 4; mi++)
#pragma unroll
        for (int ni = 0; ni < 4; ni++)
#pragma unroll
            for (int r = 0; r < 4; r++) acc[mi][ni][r] = 0.f;

    // loaders: row = tid>>1 (128 rows), 2 x 16B chunks at half-offset (tid&1)*16 + {0,8}
    const int lr = tid >> 1;
    const int lc = (tid & 1) * 16;
    const bool avalid = (m0 + lr) < M;
    long grow = 0;
    if (avalid) grow = GATHER ? (long)gidx[m0 + lr] : (long)(m0 + lr);
    const __half* Ap = A + grow * (long)lda + lc;
    const int ab = avalid ? 16 : 0;
    const __half* Bp = BT + (long)(n0 + lr) * ldb + lc;

    uint32_t adst[2], bdst[2];
    adst[0] = (uint32_t)__cvta_generic_to_shared(&As[0][lr * HST + lc]);
    adst[1] = (uint32_t)__cvta_generic_to_shared(&As[1][lr * HST + lc]);
    bdst[0] = (uint32_t)__cvta_generic_to_shared(&Bs[0][lr * HST + lc]);
    bdst[1] = (uint32_t)__cvta_generic_to_shared(&Bs[1][lr * HST + lc]);

    // ldmatrix lane address: row = wm + (lane&15), col halves = (lane>>4)*8
    uint32_t albase[2];
    {
        const int rowoff = lane & 15;
        const int coloff = (lane >> 4) * 8;
        albase[0] = (uint32_t)__cvta_generic_to_shared(&As[0][(wm + rowoff) * HST + coloff]);
        albase[1] = (uint32_t)__cvta_generic_to_shared(&As[1][(wm + rowoff) * HST + coloff]);
    }

    const int KT = Kdim / 32;

    // prologue: stage 0
    cp16(adst[0], Ap, ab);
    cp16(adst[0] + 16, Ap + 8, ab);
    cp16(bdst[0], Bp, 16);
    cp16(bdst[0] + 16, Bp + 8, 16);
    CP_COMMIT;

    for (int kt = 0; kt < KT; kt++) {
        const int cur = kt & 1;
        CP_WAIT0;
        __syncthreads();
        if (kt + 1 < KT) {
            const __half* ap = Ap + (kt + 1) * 32;
            const __half* bp = Bp + (kt + 1) * 32;
            cp16(adst[cur ^ 1], ap, ab);
            cp16(adst[cur ^ 1] + 16, ap + 8, ab);
            cp16(bdst[cur ^ 1], bp, 16);
            cp16(bdst[cur ^ 1] + 16, bp + 8, 16);
            CP_COMMIT;
        }

        const __half* bs = Bs[cur];
        const uint32_t alb = albase[cur];
#pragma unroll
        for (int ks = 0; ks < 32; ks += 16) {
            uint32_t af[4][4], bf[4][2];
#pragma unroll
            for (int mi = 0; mi < 4; mi++)
                ldsm4(af[mi], alb + (mi * 16 * HST + ks) * 2);
#pragma unroll
            for (int ni = 0; ni < 4; ni++) {
                const int base = (wn + ni * 8 + gid) * HST + ks + tig * 2;
                bf[ni][0] = *(const uint32_t*)&bs[base];
                bf[ni][1] = *(const uint32_t*)&bs[base + 8];
            }
#pragma unroll
            for (int mi = 0; mi < 4; mi++)
#pragma unroll
                for (int ni = 0; ni < 4; ni++)
                    mma_f16(acc[mi][ni], af[mi], bf[ni]);
        }
    }

    // epilogue (c0:(g,2t) c1:(g,2t+1) c2:(g+8,2t) c3:(g+8,2t+1))
#pragma unroll
    for (int mi = 0; mi < 4; mi++) {
#pragma unroll
        for (int half = 0; half < 2; half++) {
            const int row = m0 + wm + mi * 16 + gid + half * 8;
            if (row >= M) continue;
#pragma unroll
            for (int ni = 0; ni < 4; ni++) {
                const int col = n0 + wn + ni * 8 + tig * 2;
                float v0 = acc[mi][ni][half * 2 + 0];
                float v1 = acc[mi][ni][half * 2 + 1];
                if (bias) { v0 += bias[col]; v1 += bias[col + 1]; }
                if (RELU) { v0 = fmaxf(v0, 0.f); v1 = fmaxf(v1, 0.f); }
                if (WMODE == 0) {
                    *(float2*)(C + (long)row * ldc + col) = make_float2(v0, v1);
                } else {
                    *(__half2*)(Ch + (long)row * ldc + col) = __floats2half2_rn(v0, v1);
                }
            }
        }
    }
}

// ---------------- GEMM wrappers -------------------------------------------------
__global__ void __launch_bounds__(256) k_hproj3(
    const __half* a0, const __half* a1, const __half* a2,
    const __half* wt0, const __half* wt1, const __half* wt2,
    const float* bi0, const float* bi1, const float* bi2,
    float* c0, float* c1, float* c2)
{
    const __half *A, *WT;
    const float* bi;
    float* C;
    if (blockIdx.z == 0)      { A = a0; WT = wt0; bi = bi0; C = c0; }
    else if (blockIdx.z == 1) { A = a1; WT = wt1; bi = bi1; C = c1; }
    else                      { A = a2; WT = wt2; bi = bi2; C = c2; }
    hgemm<0, false, false>(A, D_, WT, D_, C, nullptr, D_, N_, D_,
                           blockIdx.x * 128, bi, nullptr);
}

__global__ void __launch_bounds__(256) k_hproj1(
    const __half* __restrict__ A, const __half* __restrict__ WT,
    const float* __restrict__ bi, float* __restrict__ C)
{
    hgemm<0, false, false>(A, D_, WT, D_, C, nullptr, D_, N_, D_,
                           blockIdx.x * 128, bi, nullptr);
}

// MoE FF1: hidden = relu(gather(x2h) @ W1[e] + b1[e]) -> fp16 g_sh
__global__ void __launch_bounds__(256) k_hff1(const float* __restrict__ B1)
{
    const int e = blockIdx.z;
    const int cnt = g_cnt[e];
    if ((int)(blockIdx.y * 128) >= cnt) return;
    const int off = g_off[e];
    hgemm<2, true, true>(
        g_x2h, D_, g_w1th + (long)e * F_ * D_, D_,
        nullptr, g_sh + (long)off * F_, F_,
        cnt, D_, blockIdx.x * 128, B1 + (long)e * F_, g_dtok + off);
}

// MoE FF2: y[dispatch_row] = hidden @ W2[e] + b2[e] -> fp32 g_y
__global__ void __launch_bounds__(256) k_hff2(const float* __restrict__ B2)
{
    const int e = blockIdx.z;
    const int cnt = g_cnt[e];
    if ((int)(blockIdx.y * 128) >= cnt) return;
    const int off = g_off[e];
    hgemm<0, false, false>(
        g_sh + (long)off * F_, F_, g_w2th + (long)e * D_ * F_, F_,
        g_y + (long)off * D_, nullptr, D_,
        cnt, F_, blockIdx.x * 128, B2 + (long)e * D_, nullptr);
}

// ---------------- converters ----------------------------------------------------
__global__ void k_cvt(const float* __restrict__ src, __half* __restrict__ dst, long n)
{
    long i = ((long)blockIdx.x * 256 + threadIdx.x) * 4;
    if (i + 3 < n) {
        float4 v = *(const float4*)(src + i);
        *(__half2*)(dst + i) = __floats2half2_rn(v.x, v.y);
        *(__half2*)(dst + i + 2) = __floats2half2_rn(v.z, v.w);
    }
}

// transpose fp32 [R][C] -> fp16 [C][R]
__global__ void k_trh(const float* __restrict__ src, __half* __restrict__ dst,
                      int R, int C)
{
    __shared__ float t[32][33];
    const long offs = (long)blockIdx.z * (long)R * C;
    src += offs; dst += offs;
    const int c0 = blockIdx.x * 32, r0 = blockIdx.y * 32;
    const int tx = threadIdx.x & 31, ty = threadIdx.x >> 5;
#pragma unroll
    for (int i = ty; i < 32; i += 8)
        t[i][tx] = src[(long)(r0 + i) * C + c0 + tx];
    __syncthreads();
#pragma unroll
    for (int i = ty; i < 32; i += 8)
        dst[(long)(c0 + i) * R + r0 + tx] = __float2half(t[tx][i]);
}

// ---------------- flash attention (tf32, unchanged; writes fp16 attn) ----------
#define QS_OFF 0
#define PS_OFF 8704
#define KS_OFF 17408
#define VS_OFF 21760
#define FL_SMEM_WORDS 26368   // *4 = 105472 bytes

__global__ void __launch_bounds__(256) k_flash()
{
    extern __shared__ float sm[];
#define QS(r, c) sm[QS_OFF + (r) * 68 + (c)]
#define PS(r, c) sm[PS_OFF + (r) * 68 + (c)]
#define KS(r, c) sm[KS_OFF + (r) * 68 + (c)]
#define VS(r, c) sm[VS_OFF + (r) * 72 + (c)]

    const int tid = threadIdx.x;
    const int w = tid >> 5;
    const int lane = tid & 31;
    const int gid = lane >> 2;
    const int tig = lane & 3;
    const int wm = w * 16;

    const int qb = blockIdx.x;
    const int z = blockIdx.y;
    const int b = z >> 4, h = z & 15;
    const int q0 = qb * 128;

    const int rowoff = lane & 15;
    const int coloff = (lane >> 4) * 4;
    const uint32_t qlb = (uint32_t)__cvta_generic_to_shared(&QS(wm + rowoff, coloff));
    const uint32_t plb = (uint32_t)__cvta_generic_to_shared(&PS(wm + rowoff, coloff));
    const int krow = lane & 7;
    const int kcol = ((lane >> 3) & 1) * 4;
    const uint32_t klb = (uint32_t)__cvta_generic_to_shared(&KS(krow, kcol));

    {
        const int r = tid >> 1;
        const int c0 = (tid & 1) * 32;
        const float* qp = g_q + ((long)(b * S_ + q0 + r)) * D_ + h * DH_ + c0;
        uint32_t qd = (uint32_t)__cvta_generic_to_shared(&QS(r, c0));
#pragma unroll
        for (int i = 0; i < 8; i++) cp16(qd + i * 16, qp + i * 4, 16);
    }

    const int ls = tid >> 2;
    const int ld0 = (tid & 3) * 16;
    const long kvb = ((long)(b * S_ + ls)) * D_ + h * DH_ + ld0;
    uint32_t kd = (uint32_t)__cvta_generic_to_shared(&KS(ls, ld0));
    uint32_t vd = (uint32_t)__cvta_generic_to_shared(&VS(ls, ld0));

    {
        const float* kp = g_k + kvb;
        const float* vp = g_v + kvb;
#pragma unroll
        for (int i = 0; i < 4; i++) {
            cp16(kd + i * 16, kp + i * 4, 16);
            cp16(vd + i * 16, vp + i * 4, 16);
        }
    }
    CP_COMMIT;

    float m0v = -3.4e38f, m1v = -3.4e38f;
    float l0 = 0.f, l1 = 0.f;
    float o[8][4];
#pragma unroll
    for (int ni = 0; ni < 8; ni++)
#pragma unroll
        for (int r = 0; r < 4; r++) o[ni][r] = 0.f;

    const int J = S_ / 64;
    for (int j = 0; j < J; j++) {
        CP_WAIT0;
        __syncthreads();

        float sacc[8][4];
#pragma unroll
        for (int ni = 0; ni < 8; ni++)
#pragma unroll
            for (int r = 0; r < 4; r++) sacc[ni][r] = 0.f;
#pragma unroll
        for (int ks = 0; ks < 64; ks += 8) {
            uint32_t af[4];
            ldsm4(af, qlb + ks * 4);
#pragma unroll
            for (int ni = 0; ni < 8; ni++) {
                uint32_t bf[2];
                ldsm2(bf, klb + (ni * 8 * 68 + ks) * 4);
                mma_tf32(sacc[ni], af, bf);
            }
        }
#pragma unroll
        for (int ni = 0; ni < 8; ni++)
#pragma unroll
            for (int r = 0; r < 4; r++) sacc[ni][r] *= 0.125f;

        float mx0 = -3.4e38f, mx1 = -3.4e38f;
#pragma unroll
        for (int ni = 0; ni < 8; ni++) {
            mx0 = fmaxf(mx0, fmaxf(sacc[ni][0], sacc[ni][1]));
            mx1 = fmaxf(mx1, fmaxf(sacc[ni][2], sacc[ni][3]));
        }
        mx0 = fmaxf(mx0, __shfl_xor_sync(0xffffffffu, mx0, 1));
        mx0 = fmaxf(mx0, __shfl_xor_sync(0xffffffffu, mx0, 2));
        mx1 = fmaxf(mx1, __shfl_xor_sync(0xffffffffu, mx1, 1));
        mx1 = fmaxf(mx1, __shfl_xor_sync(0xffffffffu, mx1, 2));
        const float mn0 = fmaxf(m0v, mx0);
        const float mn1 = fmaxf(m1v, mx1);
        const float a0 = __expf(m0v - mn0);
        const float a1 = __expf(m1v - mn1);
        m0v = mn0; m1v = mn1;

        float s0 = 0.f, s1 = 0.f;
#pragma unroll
        for (int ni = 0; ni < 8; ni++) {
            float p0 = __expf(sacc[ni][0] - mn0);
            float p1 = __expf(sacc[ni][1] - mn0);
            float p2 = __expf(sacc[ni][2] - mn1);
            float p3 = __expf(sacc[ni][3] - mn1);
            s0 += p0 + p1; s1 += p2 + p3;
            const int col = ni * 8 + tig * 2;
            PS(wm + gid, col) = p0;
            PS(wm + gid, col + 1) = p1;
            PS(wm + gid + 8, col) = p2;
            PS(wm + gid + 8, col + 1) = p3;
        }
        s0 += __shfl_xor_sync(0xffffffffu, s0, 1);
        s0 += __shfl_xor_sync(0xffffffffu, s0, 2);
        s1 += __shfl_xor_sync(0xffffffffu, s1, 1);
        s1 += __shfl_xor_sync(0xffffffffu, s1, 2);
        l0 = l0 * a0 + s0;
        l1 = l1 * a1 + s1;

#pragma unroll
        for (int ni = 0; ni < 8; ni++) {
            o[ni][0] *= a0; o[ni][1] *= a0;
            o[ni][2] *= a1; o[ni][3] *= a1;
        }
        __syncwarp();

#pragma unroll
        for (int ks = 0; ks < 64; ks += 8) {
            uint32_t af[4];
            ldsm4(af, plb + ks * 4);
#pragma unroll
            for (int ni = 0; ni < 8; ni++) {
                uint32_t bf[2];
                bf[0] = __float_as_uint(VS(ks + tig, ni * 8 + gid));
                bf[1] = __float_as_uint(VS(ks + tig + 4, ni * 8 + gid));
                mma_tf32(o[ni], af, bf);
            }
        }
        __syncthreads();

        if (j + 1 < J) {
            const float* kp = g_k + kvb + (long)(j + 1) * 64 * D_;
            const float* vp = g_v + kvb + (long)(j + 1) * 64 * D_;
#pragma unroll
            for (int i = 0; i < 4; i++) {
                cp16(kd + i * 16, kp + i * 4, 16);
                cp16(vd + i * 16, vp + i * 4, 16);
            }
            CP_COMMIT;
        }
    }

    // write O (normalized) as fp16 for the output projection
    const float inv0 = 1.f / l0;
    const float inv1 = 1.f / l1;
    const long r0 = (long)(b * S_ + q0 + wm + gid) * D_ + h * DH_;
    const long r1 = r0 + 8 * D_;
#pragma unroll
    for (int ni = 0; ni < 8; ni++) {
        const int col = ni * 8 + tig * 2;
        *(__half2*)(g_attnh + r0 + col) = __floats2half2_rn(o[ni][0] * inv0, o[ni][1] * inv0);
        *(__half2*)(g_attnh + r1 + col) = __floats2half2_rn(o[ni][2] * inv1, o[ni][3] * inv1);
    }
#undef QS
#undef PS
#undef KS
#undef VS
}

// ---------------- elementwise / LN ---------------------------------------------
__global__ void k_zero()
{
    int i = threadIdx.x;
    if (i < E_) { g_cnt[i] = 0; g_cur[i] = 0; g_loadcnt[i] = 0; }
}

// out = LN(a + b); outh = fp16 shadow (may be null)
__global__ void k_addln(const float* __restrict__ a, const float* __restrict__ b,
                        const float* __restrict__ g, const float* __restrict__ be,
                        float* __restrict__ out, __half* __restrict__ outh)
{
    __shared__ float buf[D_];
    __shared__ float red[256];
    const int t = blockIdx.x;
    const int tid = threadIdx.x;
    const float* pa = a + (long)t * D_;
    const float* pb = b + (long)t * D_;
    float s = 0.f;
    for (int i = tid; i < D_; i += 256) { float v = pa[i] + pb[i]; buf[i] = v; s += v; }
    red[tid] = s; __syncthreads();
    for (int o = 128; o > 0; o >>= 1) { if (tid < o) red[tid] += red[tid + o]; __syncthreads(); }
    float mean = red[0] * (1.f / D_);
    __syncthreads();
    float vs = 0.f;
    for (int i = tid; i < D_; i += 256) { float d = buf[i] - mean; vs += d * d; }
    red[tid] = vs; __syncthreads();
    for (int o = 128; o > 0; o >>= 1) { if (tid < o) red[tid] += red[tid + o]; __syncthreads(); }
    float rstd = rsqrtf(red[0] * (1.f / D_) + 1e-5f);
    float* po = out + (long)t * D_;
    __half* ph = outh ? (outh + (long)t * D_) : (__half*)0;
    for (int i = tid; i < D_; i += 256) {
        float v = (buf[i] - mean) * rstd * g[i] + be[i];
        po[i] = v;
        if (ph) ph[i] = __float2half(v);
    }
}

// final LN fused with MoE combine: out = LN(x2 + g0*y[d0] + g1*y[d1])
__global__ void k_addln_moe(const float* __restrict__ a,
                            const float* __restrict__ g, const float* __restrict__ be,
                            float* __restrict__ out)
{
    __shared__ float buf[D_];
    __shared__ float red[256];
    const int t = blockIdx.x;
    const int tid = threadIdx.x;
    const float* pa = a + (long)t * D_;
    const float* y0 = g_y + (long)g_drow[t * 2] * D_;
    const float* y1 = g_y + (long)g_drow[t * 2 + 1] * D_;
    const float gt0 = g_gate[t * 2];
    const float gt1 = g_gate[t * 2 + 1];
    float s = 0.f;
    for (int i = tid; i < D_; i += 256) {
        float v = pa[i] + gt0 * y0[i] + gt1 * y1[i];
        buf[i] = v; s += v;
    }
    red[tid] = s; __syncthreads();
    for (int o = 128; o > 0; o >>= 1) { if (tid < o) red[tid] += red[tid + o]; __syncthreads(); }
    float mean = red[0] * (1.f / D_);
    __syncthreads();
    float vs = 0.f;
    for (int i = tid; i < D_; i += 256) { float d = buf[i] - mean; vs += d * d; }
    red[tid] = vs; __syncthreads();
    for (int o = 128; o > 0; o >>= 1) { if (tid < o) red[tid] += red[tid + o]; __syncthreads(); }
    float rstd = rsqrtf(red[0] * (1.f / D_) + 1e-5f);
    float* po = out + (long)t * D_;
    for (int i = tid; i < D_; i += 256)
        po[i] = (buf[i] - mean) * rstd * g[i] + be[i];
}

// ---------------- router / dispatch / aux --------------------------------------
__device__ __forceinline__ void router_core(const float* __restrict__ x,
                                            const float* __restrict__ rw,
                                            const float* __restrict__ rb,
                                            int lane, float* probs_out,
                                            int* i1_out, int* i2_out)
{
    float le[E_];
#pragma unroll
    for (int e = 0; e < E_; e++) le[e] = 0.f;
    for (int d0 = lane * 4; d0 < D_; d0 += 128) {
        float4 xv = *(const float4*)(x + d0);
        float xa[4] = {xv.x, xv.y, xv.z, xv.w};
#pragma unroll
        for (int r = 0; r < 4; r++) {
            const float* w = rw + (long)(d0 + r) * E_;
            float4 w0 = *(const float4*)(w);
            float4 w1 = *(const float4*)(w + 4);
            le[0] = fmaf(xa[r], w0.x, le[0]); le[1] = fmaf(xa[r], w0.y, le[1]);
            le[2] = fmaf(xa[r], w0.z, le[2]); le[3] = fmaf(xa[r], w0.w, le[3]);
            le[4] = fmaf(xa[r], w1.x, le[4]); le[5] = fmaf(xa[r], w1.y, le[5]);
            le[6] = fmaf(xa[r], w1.z, le[6]); le[7] = fmaf(xa[r], w1.w, le[7]);
        }
    }
#pragma unroll
    for (int e = 0; e < E_; e++)
        for (int o = 16; o > 0; o >>= 1) le[e] += __shfl_xor_sync(0xffffffffu, le[e], o);
    float mx = -3.4e38f;
#pragma unroll
    for (int e = 0; e < E_; e++) { le[e] += rb[e]; mx = fmaxf(mx, le[e]); }
    float sum = 0.f;
#pragma unroll
    for (int e = 0; e < E_; e++) { le[e] = expf(le[e] - mx); sum += le[e]; }
    float inv = 1.f / sum;
#pragma unroll
    for (int e = 0; e < E_; e++) { le[e] *= inv; probs_out[e] = le[e]; }
    int i1 = 0;
    for (int e = 1; e < E_; e++) if (le[e] > le[i1]) i1 = e;
    int i2 = (i1 == 0) ? 1 : 0;
    for (int e = 0; e < E_; e++) if (e != i1 && le[e] > le[i2]) i2 = e;
    *i1_out = i1; *i2_out = i2;
}

__global__ void k_router(const float* __restrict__ rw, const float* __restrict__ rb)
{
    const int warp = threadIdx.x >> 5, lane = threadIdx.x & 31;
    const int t = blockIdx.x * 8 + warp;
    if (t >= N_) return;
    float probs[E_]; int i1, i2;
    router_core(g_x2 + (long)t * D_, rw, rb, lane, probs, &i1, &i2);
    if (lane == 0) {
        float gs = probs[i1] + probs[i2];
        g_topi[t * 2] = i1; g_topi[t * 2 + 1] = i2;
        g_gate[t * 2] = probs[i1] / gs; g_gate[t * 2 + 1] = probs[i2] / gs;
        atomicAdd(&g_cnt[i1], 1); atomicAdd(&g_cnt[i2], 1);
    }
}

__global__ void k_scan()
{
    if (threadIdx.x == 0) {
        int s = 0;
        for (int e = 0; e < E_; e++) { g_off[e] = s; s += g_cnt[e]; }
    }
}

__global__ void k_fill()
{
    int t = blockIdx.x * 256 + threadIdx.x;
    if (t >= N_) return;
#pragma unroll
    for (int k = 0; k < K_; k++) {
        int e = g_topi[t * K_ + k];
        int p = atomicAdd(&g_cur[e], 1);
        int d = g_off[e] + p;
        g_dtok[d] = t;
        g_drow[t * K_ + k] = d;
    }
}

__global__ void k_aux_router(const float* __restrict__ X,
                             const float* __restrict__ rw, const float* __restrict__ rb)
{
    const int warp = threadIdx.x >> 5, lane = threadIdx.x & 31;
    const int t = blockIdx.x * 8 + warp;
    if (t >= N_) return;
    float probs[E_]; int i1, i2;
    router_core(X + (long)t * D_, rw, rb, lane, probs, &i1, &i2);
    if (lane == 0) {
#pragma unroll
        for (int e = 0; e < E_; e++) g_probs[t * E_ + e] = probs[e];
        atomicAdd(&g_loadcnt[i1], 1); atomicAdd(&g_loadcnt[i2], 1);
    }
}

__global__ void k_aux_reduce(float* __restrict__ out, int write)
{
    __shared__ float red[256];
    const int tid = threadIdx.x;
    float imp[E_];
#pragma unroll
    for (int e = 0; e < E_; e++) imp[e] = 0.f;
    for (int t = tid; t < N_; t += 256)
#pragma unroll
        for (int e = 0; e < E_; e++) imp[e] += g_probs[t * E_ + e];
    float aux = 0.f;
    for (int e = 0; e < E_; e++) {
        red[tid] = imp[e]; __syncthreads();
        for (int o = 128; o > 0; o >>= 1) { if (tid < o) red[tid] += red[tid + o]; __syncthreads(); }
        if (tid == 0)
            aux += (red[0] / (float)N_) * ((float)g_loadcnt[e] / (float)(N_ * K_));
        __syncthreads();
    }
    if (tid == 0 && write) out[ND_] = aux * (float)E_;
}

// ---------------- launch ------------------------------------------------------
extern "C" void kernel_launch(void* const* d_in, const int* in_sizes, int n_in,
                              void* d_out, int out_size)
{
    (void)in_sizes; (void)n_in;
    const float* x     = (const float*)d_in[0];
    const float* enc   = (const float*)d_in[1];
    const float* sa_wq = (const float*)d_in[2];
    const float* sa_bq = (const float*)d_in[3];
    const float* sa_wk = (const float*)d_in[4];
    const float* sa_bk = (const float*)d_in[5];
    const float* sa_wv = (const float*)d_in[6];
    const float* sa_bv = (const float*)d_in[7];
    const float* sa_wo = (const float*)d_in[8];
    const float* sa_bo = (const float*)d_in[9];
    const float* ca_wq = (const float*)d_in[10];
    const float* ca_bq = (const float*)d_in[11];
    const float* ca_wk = (const float*)d_in[12];
    const float* ca_bk = (const float*)d_in[13];
    const float* ca_wv = (const float*)d_in[14];
    const float* ca_bv = (const float*)d_in[15];
    const float* ca_wo = (const float*)d_in[16];
    const float* ca_bo = (const float*)d_in[17];
    const float* n1_g  = (const float*)d_in[18];
    const float* n1_b  = (const float*)d_in[19];
    const float* n2_g  = (const float*)d_in[20];
    const float* n2_b  = (const float*)d_in[21];
    const float* n3_g  = (const float*)d_in[22];
    const float* n3_b  = (const float*)d_in[23];
    const float* r_w   = (const float*)d_in[24];
    const float* r_b   = (const float*)d_in[25];
    const float* e_w1  = (const float*)d_in[26];
    const float* e_b1  = (const float*)d_in[27];
    const float* e_w2  = (const float*)d_in[28];
    const float* e_b2  = (const float*)d_in[29];
    float* out = (float*)d_out;

    float *pq, *pk, *pv, *pt, *px1, *px2;
    __half *pxh, *pench, *pattnh, *px1h, *px2h, *pwth, *pw1th, *pw2th;
    cudaGetSymbolAddress((void**)&pq, g_q);
    cudaGetSymbolAddress((void**)&pk, g_k);
    cudaGetSymbolAddress((void**)&pv, g_v);
    cudaGetSymbolAddress((void**)&pt, g_t);
    cudaGetSymbolAddress((void**)&px1, g_x1);
    cudaGetSymbolAddress((void**)&px2, g_x2);
    cudaGetSymbolAddress((void**)&pxh, g_xh);
    cudaGetSymbolAddress((void**)&pench, g_ench);
    cudaGetSymbolAddress((void**)&pattnh, g_attnh);
    cudaGetSymbolAddress((void**)&px1h, g_x1h);
    cudaGetSymbolAddress((void**)&px2h, g_x2h);
    cudaGetSymbolAddress((void**)&pwth, g_wth);
    cudaGetSymbolAddress((void**)&pw1th, g_w1th);
    cudaGetSymbolAddress((void**)&pw2th, g_w2th);

    static int s_attr_done = 0;
    if (!s_attr_done) {
        cudaFuncSetAttribute(k_flash, cudaFuncAttributeMaxDynamicSharedMemorySize,
                             FL_SMEM_WORDS * 4);
        s_attr_done = 1;
    }

    dim3 blk(256);
    dim3 gP3(D_ / 128, N_ / 128, 3);           // (8, 32, 3)
    dim3 gP1(D_ / 128, N_ / 128);              // (8, 32)
    dim3 gFlash(S_ / 128, BH_);                // (16, 32)
    dim3 gTr(D_ / 32, D_ / 32);                // (32, 32)

    k_zero<<<1, 32>>>();

    // ---- converts + weight transposes (fp32 -> fp16) ----
    k_cvt<<<(int)(ND_ / 1024), blk>>>(x, pxh, ND_);
    k_cvt<<<(int)(ND_ / 1024), blk>>>(enc, pench, ND_);
    const float* ws[8] = {sa_wq, sa_wk, sa_wv, sa_wo, ca_wq, ca_wk, ca_wv, ca_wo};
    for (int i = 0; i < 8; i++)
        k_trh<<<gTr, blk>>>(ws[i], pwth + (long)i * D_ * D_, D_, D_);
    k_trh<<<dim3(F_ / 32, D_ / 32, E_), blk>>>(e_w1, pw1th, D_, F_);
    k_trh<<<dim3(D_ / 32, F_ / 32, E_), blk>>>(e_w2, pw2th, F_, D_);

    // ---- self attention ----
    k_hproj3<<<gP3, blk>>>(pxh, pxh, pxh,
        pwth + 0L * D_ * D_, pwth + 1L * D_ * D_, pwth + 2L * D_ * D_,
        sa_bq, sa_bk, sa_bv, pq, pk, pv);
    k_flash<<<gFlash, blk, FL_SMEM_WORDS * 4>>>();
    k_hproj1<<<gP1, blk>>>(pattnh, pwth + 3L * D_ * D_, sa_bo, pt);
    k_addln<<<N_, blk>>>(x, pt, n1_g, n1_b, px1, px1h);

    // ---- cross attention ----
    k_hproj3<<<gP3, blk>>>(px1h, pench, pench,
        pwth + 4L * D_ * D_, pwth + 5L * D_ * D_, pwth + 6L * D_ * D_,
        ca_bq, ca_bk, ca_bv, pq, pk, pv);
    k_flash<<<gFlash, blk, FL_SMEM_WORDS * 4>>>();
    k_hproj1<<<gP1, blk>>>(pattnh, pwth + 7L * D_ * D_, ca_bo, pt);
    k_addln<<<N_, blk>>>(px1, pt, n2_g, n2_b, px2, px2h);

    // ---- MoE (sparse top-2 dispatch) ----
    k_router<<<N_ / 8, blk>>>(r_w, r_b);
    k_scan<<<1, 32>>>();
    k_fill<<<N_ / 256, blk>>>();
    k_hff1<<<dim3(F_ / 128, 64, E_), blk>>>(e_b1);
    k_hff2<<<dim3(D_ / 128, 64, E_), blk>>>(e_b2);
    k_addln_moe<<<N_, blk>>>(px2, n3_g, n3_b, out);

    // ---- aux loss on final output ----
    k_aux_router<<<N_ / 8, blk>>>(out, r_w, r_b);
    k_aux_reduce<<<1, blk>>>(out, ((long)out_size > ND_) ? 1 : 0);
}